// round 1
// baseline (speedup 1.0000x reference)
#include <cuda_runtime.h>
#include <cuda_bf16.h>

// ----------------------------------------------------------------------------
// CausalAttention: b=4, n=2048, d_in=d_out=1024, fp32.
//   Q = x@Wq, K = x@Wk, V = x@Wv
//   S = Q@K^T (causal), P = softmax(S/sqrt(d)), out = P@V
// Baseline: fp32 register-blocked SGEMM (128x128x8, 8x8 per thread).
// ----------------------------------------------------------------------------

#define BM 128
#define BN 128
#define BK 8
#define TM 8
#define TN 8
#define NTHREADS 256

#define B_SZ 4
#define N_SZ 2048
#define D_SZ 1024

// Scratch (static device globals; allocation-free per harness rules).
__device__ float g_Q[(size_t)B_SZ * N_SZ * D_SZ];   // 32 MB
__device__ float g_K[(size_t)B_SZ * N_SZ * D_SZ];   // 32 MB
__device__ float g_V[(size_t)B_SZ * N_SZ * D_SZ];   // 32 MB
__device__ float g_S[(size_t)B_SZ * N_SZ * N_SZ];   // 64 MB

// ----------------------------------------------------------------------------
// C[M,N] = A[M,K] @ B[K,N], row-major, optional per-z strides and causal
// k-limit (for P@V: query block row `by` only needs k < (by+1)*BM).
// Requires M%BM==0, N%BN==0, K%BK==0, 16B-aligned pointers.
// ----------------------------------------------------------------------------
__global__ __launch_bounds__(NTHREADS)
void sgemm_nn(const float* __restrict__ A, const float* __restrict__ B,
              float* __restrict__ C, int M, int N, int K,
              long long strideA, long long strideB, long long strideC,
              int causalK)
{
    const int bx = blockIdx.x;   // block col (N)
    const int by = blockIdx.y;   // block row (M)
    const int bz = blockIdx.z;   // batch

    A += bz * strideA;
    B += bz * strideB;
    C += bz * strideC;

    int kEnd = K;
    if (causalK) {
        int lim = (by + 1) * BM;
        kEnd = lim < K ? lim : K;
    }

    __shared__ float As[BK * BM];   // transposed A tile
    __shared__ float Bs[BK * BN];

    const int tid = threadIdx.x;
    const int threadCol = tid % (BN / TN);   // 0..15
    const int threadRow = tid / (BN / TN);   // 0..15

    const int innerRowA = tid / (BK / 4);    // 0..127
    const int innerColA = tid % (BK / 4);    // 0..1
    const int innerRowB = tid / (BN / 4);    // 0..7
    const int innerColB = tid % (BN / 4);    // 0..31

    const float* Ab = A + (long long)(by * BM) * K;
    const float* Bb = B + bx * BN;
    float*       Cb = C + (long long)(by * BM) * N + bx * BN;

    float acc[TM][TN] = {};
    float regM[TM], regN[TN];

    for (int k0 = 0; k0 < kEnd; k0 += BK) {
        float4 a4 = *reinterpret_cast<const float4*>(
            Ab + (long long)innerRowA * K + k0 + innerColA * 4);
        As[(innerColA * 4 + 0) * BM + innerRowA] = a4.x;
        As[(innerColA * 4 + 1) * BM + innerRowA] = a4.y;
        As[(innerColA * 4 + 2) * BM + innerRowA] = a4.z;
        As[(innerColA * 4 + 3) * BM + innerRowA] = a4.w;

        float4 b4 = *reinterpret_cast<const float4*>(
            Bb + (long long)(k0 + innerRowB) * N + innerColB * 4);
        *reinterpret_cast<float4*>(&Bs[innerRowB * BN + innerColB * 4]) = b4;

        __syncthreads();

        #pragma unroll
        for (int k = 0; k < BK; k++) {
            #pragma unroll
            for (int i = 0; i < TM; i++) regM[i] = As[k * BM + threadRow * TM + i];
            #pragma unroll
            for (int j = 0; j < TN; j++) regN[j] = Bs[k * BN + threadCol * TN + j];
            #pragma unroll
            for (int i = 0; i < TM; i++)
                #pragma unroll
                for (int j = 0; j < TN; j++)
                    acc[i][j] += regM[i] * regN[j];
        }
        __syncthreads();
    }

    #pragma unroll
    for (int i = 0; i < TM; i++) {
        #pragma unroll
        for (int j = 0; j < TN; j += 4) {
            float4 v = make_float4(acc[i][j], acc[i][j + 1], acc[i][j + 2], acc[i][j + 3]);
            *reinterpret_cast<float4*>(
                Cb + (long long)(threadRow * TM + i) * N + threadCol * TN + j) = v;
        }
    }
}

// ----------------------------------------------------------------------------
// S[z] = Q[z] @ K[z]^T ; Q,K: [n, d] row-major per batch. Blocks strictly
// above the diagonal are skipped (softmax zero-fills them later).
// ----------------------------------------------------------------------------
__global__ __launch_bounds__(NTHREADS)
void sgemm_nt_causal(const float* __restrict__ Q, const float* __restrict__ Km,
                     float* __restrict__ S, int n, int d)
{
    const int bx = blockIdx.x;   // key block
    const int by = blockIdx.y;   // query block
    const int bz = blockIdx.z;   // batch
    if (bx > by) return;         // entirely above diagonal

    const float* A = Q  + (long long)bz * n * d + (long long)(by * BM) * d;
    const float* B = Km + (long long)bz * n * d + (long long)(bx * BN) * d;
    float*       C = S  + (long long)bz * n * n + (long long)(by * BM) * n + bx * BN;

    __shared__ float As[BK * BM];
    __shared__ float Bs[BK * BN];

    const int tid = threadIdx.x;
    const int threadCol = tid % (BN / TN);
    const int threadRow = tid / (BN / TN);

    const int innerRow = tid / (BK / 4);   // 0..127
    const int innerCol = tid % (BK / 4);   // 0..1

    float acc[TM][TN] = {};
    float regM[TM], regN[TN];

    for (int k0 = 0; k0 < d; k0 += BK) {
        float4 a4 = *reinterpret_cast<const float4*>(
            A + (long long)innerRow * d + k0 + innerCol * 4);
        As[(innerCol * 4 + 0) * BM + innerRow] = a4.x;
        As[(innerCol * 4 + 1) * BM + innerRow] = a4.y;
        As[(innerCol * 4 + 2) * BM + innerRow] = a4.z;
        As[(innerCol * 4 + 3) * BM + innerRow] = a4.w;

        float4 b4 = *reinterpret_cast<const float4*>(
            B + (long long)innerRow * d + k0 + innerCol * 4);
        Bs[(innerCol * 4 + 0) * BN + innerRow] = b4.x;
        Bs[(innerCol * 4 + 1) * BN + innerRow] = b4.y;
        Bs[(innerCol * 4 + 2) * BN + innerRow] = b4.z;
        Bs[(innerCol * 4 + 3) * BN + innerRow] = b4.w;

        __syncthreads();

        #pragma unroll
        for (int k = 0; k < BK; k++) {
            #pragma unroll
            for (int i = 0; i < TM; i++) regM[i] = As[k * BM + threadRow * TM + i];
            #pragma unroll
            for (int j = 0; j < TN; j++) regN[j] = Bs[k * BN + threadCol * TN + j];
            #pragma unroll
            for (int i = 0; i < TM; i++)
                #pragma unroll
                for (int j = 0; j < TN; j++)
                    acc[i][j] += regM[i] * regN[j];
        }
        __syncthreads();
    }

    #pragma unroll
    for (int i = 0; i < TM; i++) {
        #pragma unroll
        for (int j = 0; j < TN; j += 4) {
            float4 v = make_float4(acc[i][j], acc[i][j + 1], acc[i][j + 2], acc[i][j + 3]);
            *reinterpret_cast<float4*>(
                C + (long long)(threadRow * TM + i) * n + threadCol * TN + j) = v;
        }
    }
}

// ----------------------------------------------------------------------------
// Causal row softmax in place on S. Row i uses elements [0, i]; elements
// (i, n) are set to exactly 0 so the P@V GEMM can read full rows.
// ----------------------------------------------------------------------------
__global__ __launch_bounds__(256)
void softmax_causal(float* __restrict__ S, int n, float scale)
{
    const int i = blockIdx.x;     // query row
    const int b = blockIdx.y;     // batch
    float* row = S + ((long long)b * n + i) * n;
    const int L = i + 1;
    const int tid = threadIdx.x;

    __shared__ float red[8];
    __shared__ float s_bcast;

    // Pass 1: max of scaled scores
    float m = -3.0e38f;
    for (int j = tid; j < L; j += 256) m = fmaxf(m, row[j] * scale);
    #pragma unroll
    for (int o = 16; o > 0; o >>= 1) m = fmaxf(m, __shfl_xor_sync(0xffffffffu, m, o));
    if ((tid & 31) == 0) red[tid >> 5] = m;
    __syncthreads();
    if (tid < 32) {
        float v = (tid < 8) ? red[tid] : -3.0e38f;
        #pragma unroll
        for (int o = 16; o > 0; o >>= 1) v = fmaxf(v, __shfl_xor_sync(0xffffffffu, v, o));
        if (tid == 0) s_bcast = v;
    }
    __syncthreads();
    m = s_bcast;

    // Pass 2: exponentiate (store back), accumulate sum
    float sum = 0.0f;
    for (int j = tid; j < L; j += 256) {
        float e = __expf(row[j] * scale - m);
        row[j] = e;
        sum += e;
    }
    #pragma unroll
    for (int o = 16; o > 0; o >>= 1) sum += __shfl_xor_sync(0xffffffffu, sum, o);
    __syncthreads();
    if ((tid & 31) == 0) red[tid >> 5] = sum;
    __syncthreads();
    if (tid < 32) {
        float v = (tid < 8) ? red[tid] : 0.0f;
        #pragma unroll
        for (int o = 16; o > 0; o >>= 1) v += __shfl_xor_sync(0xffffffffu, v, o);
        if (tid == 0) s_bcast = v;
    }
    __syncthreads();
    const float inv = 1.0f / s_bcast;

    // Pass 3: normalize valid region, hard-zero masked region
    for (int j = tid; j < n; j += 256)
        row[j] = (j < L) ? row[j] * inv : 0.0f;
}

// ----------------------------------------------------------------------------
extern "C" void kernel_launch(void* const* d_in, const int* in_sizes, int n_in,
                              void* d_out, int out_size)
{
    const float* x  = (const float*)d_in[0];
    const float* Wq = (const float*)d_in[1];
    const float* Wk = (const float*)d_in[2];
    const float* Wv = (const float*)d_in[3];
    float* out = (float*)d_out;

    const int b = B_SZ, n = N_SZ, d = D_SZ;

    float *Q, *K, *V, *S;
    cudaGetSymbolAddress((void**)&Q, g_Q);
    cudaGetSymbolAddress((void**)&K, g_K);
    cudaGetSymbolAddress((void**)&V, g_V);
    cudaGetSymbolAddress((void**)&S, g_S);

    const dim3 blk(NTHREADS);

    // 1) QKV projections: [b*n, d] = [b*n, d] @ [d, d]
    const dim3 gQKV(d / BN, (b * n) / BM, 1);
    sgemm_nn<<<gQKV, blk>>>(x, Wq, Q, b * n, d, d, 0, 0, 0, 0);
    sgemm_nn<<<gQKV, blk>>>(x, Wk, K, b * n, d, d, 0, 0, 0, 0);
    sgemm_nn<<<gQKV, blk>>>(x, Wv, V, b * n, d, d, 0, 0, 0, 0);

    // 2) Scores: S[z] = Q[z] @ K[z]^T  (upper-triangle blocks skipped)
    const dim3 gS(n / BN, n / BM, b);
    sgemm_nt_causal<<<gS, blk>>>(Q, K, S, n, d);

    // 3) Softmax with 1/sqrt(d) scale; zero-fills masked region
    softmax_causal<<<dim3(n, b), 256>>>(S, n, 1.0f / 32.0f);

    // 4) out[z] = P[z] @ V[z]  (k-limited by causality)
    const dim3 gO(d / BN, n / BM, b);
    sgemm_nn<<<gO, blk>>>(S, V, out, n, d, n,
                          (long long)n * n, (long long)n * d, (long long)n * d, 1);
}

// round 3
// speedup vs baseline: 2.7323x; 2.7323x over previous
#include <cuda_runtime.h>
#include <cuda_bf16.h>
#include <cstdint>

// ============================================================================
// CausalAttention b=4, n=2048, d=1024 — mma.sync bf16 split-precision pipeline
// (compute_100 target: no tcgen05; HMMA + cp.async + ldmatrix).
//   C = Ah@Bh^T + Ah@Bl^T + Al@Bh^T  (fp32 accumulate)
// ============================================================================

#define B_SZ 4
#define N_SZ 2048
#define D_SZ 1024
#define MT 128      // CTA tile M
#define NTT 128     // CTA tile N
#define KC 32       // K chunk (bf16 elems)
#define NTHREADS 256

typedef __nv_bfloat16 bf16;

// ---------------- scratch (static device globals) ----------------
__device__ bf16  g_xh [(size_t)B_SZ*N_SZ*D_SZ];
__device__ bf16  g_xl [(size_t)B_SZ*N_SZ*D_SZ];
__device__ bf16  g_Wqh[(size_t)D_SZ*D_SZ];
__device__ bf16  g_Wql[(size_t)D_SZ*D_SZ];
__device__ bf16  g_Wkh[(size_t)D_SZ*D_SZ];
__device__ bf16  g_Wkl[(size_t)D_SZ*D_SZ];
__device__ bf16  g_Wvh[(size_t)D_SZ*D_SZ];
__device__ bf16  g_Wvl[(size_t)D_SZ*D_SZ];
__device__ bf16  g_Qh [(size_t)B_SZ*N_SZ*D_SZ];
__device__ bf16  g_Ql [(size_t)B_SZ*N_SZ*D_SZ];
__device__ bf16  g_Kh [(size_t)B_SZ*N_SZ*D_SZ];
__device__ bf16  g_Kl [(size_t)B_SZ*N_SZ*D_SZ];
__device__ bf16  g_Vth[(size_t)B_SZ*D_SZ*N_SZ];   // V^T per batch [d, n]
__device__ bf16  g_Vtl[(size_t)B_SZ*D_SZ*N_SZ];
__device__ float g_S  [(size_t)B_SZ*N_SZ*N_SZ];
__device__ bf16  g_Ph [(size_t)B_SZ*N_SZ*N_SZ];
__device__ bf16  g_Pl [(size_t)B_SZ*N_SZ*N_SZ];

// ---------------- low-level helpers (all compute_100-legal) ----------------
__device__ __forceinline__ uint32_t smem_u32(const void* p) {
    uint32_t a;
    asm("{ .reg .u64 t; cvta.to.shared.u64 t, %1; cvt.u32.u64 %0, t; }" : "=r"(a) : "l"(p));
    return a;
}
__device__ __forceinline__ void cp16(uint32_t dst, const void* src) {
    asm volatile("cp.async.cg.shared.global [%0], [%1], 16;" :: "r"(dst), "l"(src));
}
#define CP_COMMIT() asm volatile("cp.async.commit_group;" ::: "memory")
#define CP_WAIT(n)  asm volatile("cp.async.wait_group %0;" :: "n"(n) : "memory")

__device__ __forceinline__ void ldm_x4(uint32_t* r, uint32_t addr) {
    asm volatile("ldmatrix.sync.aligned.m8n8.x4.shared.b16 {%0,%1,%2,%3}, [%4];"
                 : "=r"(r[0]), "=r"(r[1]), "=r"(r[2]), "=r"(r[3]) : "r"(addr));
}
__device__ __forceinline__ void mma16(float* c, const uint32_t* a, uint32_t b0, uint32_t b1) {
    asm volatile("mma.sync.aligned.m16n8k16.row.col.f32.bf16.bf16.f32 "
                 "{%0,%1,%2,%3}, {%4,%5,%6,%7}, {%8,%9}, {%0,%1,%2,%3};"
                 : "+f"(c[0]), "+f"(c[1]), "+f"(c[2]), "+f"(c[3])
                 : "r"(a[0]), "r"(a[1]), "r"(a[2]), "r"(a[3]), "r"(b0), "r"(b1));
}

// smem layout: 2 stages x 4 tiles (Ah,Al,Bh,Bl), each tile 128 rows x 80B pitch
static constexpr uint32_t PITCH   = 80;         // 64B data + 16B pad (bank-shift 20 words)
static constexpr uint32_t TILE_B  = 128 * PITCH;   // 10240
static constexpr uint32_t STAGE_B = 4 * TILE_B;    // 40960
static constexpr uint32_t OFF_AH = 0, OFF_AL = TILE_B, OFF_BH = 2*TILE_B, OFF_BL = 3*TILE_B;
static constexpr uint32_t SMEM_SZ = 2 * STAGE_B;   // 81920

// ----------------------------------------------------------------------------
// C[M,N] = Ah@Bh^T + Ah@Bl^T + Al@Bh^T.  A:[M,K] row-major, B:[N,K] row-major.
// EPI: 0 = fp32 C (ldc,+strideC), 1 = bf16 hi/lo C (ldc), 2 = bf16 hi/lo V^T.
// ----------------------------------------------------------------------------
template <int EPI>
__global__ __launch_bounds__(NTHREADS, 2)
void gemm_mma(const bf16* __restrict__ Ah, const bf16* __restrict__ Al,
              const bf16* __restrict__ Bh, const bf16* __restrict__ Bl,
              void* C0, void* C1, int Kdim, int ldc,
              long long sA, long long sB, long long sC,
              int causalSkip, int causalKlim)
{
    const int bx = blockIdx.x, by = blockIdx.y, bz = blockIdx.z;
    if (causalSkip && bx > by) return;

    extern __shared__ char smem[];
    const uint32_t su = smem_u32(smem);
    const int tid = threadIdx.x;
    const int lane = tid & 31, wid = tid >> 5;
    const int wm = wid & 3, wn = wid >> 2;      // 4x2 warp grid

    int kEnd = Kdim;
    if (causalKlim) { int lim = (by + 1) * MT; kEnd = lim < Kdim ? lim : Kdim; }
    const int nchunks = kEnd / KC;

    const bf16* pAh = Ah + bz * sA + (long long)(by * MT) * Kdim;
    const bf16* pAl = Al + bz * sA + (long long)(by * MT) * Kdim;
    const bf16* pBh = Bh + bz * sB + (long long)(bx * NTT) * Kdim;
    const bf16* pBl = Bl + bz * sB + (long long)(bx * NTT) * Kdim;

    // cp.async mapping: 512 16B-chunks per tile, 2 per thread per tile
    const int ld_row0 = tid >> 2;          // chunk row (it=0)
    const int ld_c4   = tid & 3;           // 16B column within 64B row

    // ldmatrix address components
    const int a_row = wm * 32 + (lane & 15);
    const int a_k8  = (lane >> 4) * 16;    // bytes: +8 halves
    const int b_row = wn * 64 + ((lane >> 4) << 3) + (lane & 7);
    const int b_k8  = ((lane >> 3) & 1) * 16;

    float acc[2][8][4] = {};

    auto load_chunk = [&](int stage, int k0) {
        const uint32_t sb = su + stage * STAGE_B;
        #pragma unroll
        for (int it = 0; it < 2; it++) {
            const int row = ld_row0 + it * 64;
            const uint32_t soff = (uint32_t)row * PITCH + ld_c4 * 16;
            const long long goff = (long long)row * Kdim + k0 + ld_c4 * 8;
            cp16(sb + OFF_AH + soff, pAh + goff);
            cp16(sb + OFF_AL + soff, pAl + goff);
            cp16(sb + OFF_BH + soff, pBh + goff);
            cp16(sb + OFF_BL + soff, pBl + goff);
        }
    };

    load_chunk(0, 0);
    CP_COMMIT();

    for (int i = 0; i < nchunks; i++) {
        if (i + 1 < nchunks) {
            load_chunk((i + 1) & 1, (i + 1) * KC);
            CP_COMMIT();
            CP_WAIT(1);
        } else {
            CP_WAIT(0);
        }
        __syncthreads();

        const uint32_t sb = su + (i & 1) * STAGE_B;
        #pragma unroll
        for (int ks = 0; ks < 2; ks++) {
            const uint32_t kB = ks * 32;           // 16 halves = 32B
            uint32_t ah[2][4], al[2][4], bb[4][4];
            #pragma unroll
            for (int mt = 0; mt < 2; mt++) {
                ldm_x4(ah[mt], sb + OFF_AH + (uint32_t)(a_row + mt * 16) * PITCH + kB + a_k8);
                ldm_x4(al[mt], sb + OFF_AL + (uint32_t)(a_row + mt * 16) * PITCH + kB + a_k8);
            }
            #pragma unroll
            for (int ntp = 0; ntp < 4; ntp++)
                ldm_x4(bb[ntp], sb + OFF_BH + (uint32_t)(b_row + ntp * 16) * PITCH + kB + b_k8);
            #pragma unroll
            for (int mt = 0; mt < 2; mt++)
                #pragma unroll
                for (int nt = 0; nt < 8; nt++) {
                    mma16(acc[mt][nt], ah[mt], bb[nt >> 1][(nt & 1) * 2], bb[nt >> 1][(nt & 1) * 2 + 1]);
                    mma16(acc[mt][nt], al[mt], bb[nt >> 1][(nt & 1) * 2], bb[nt >> 1][(nt & 1) * 2 + 1]);
                }
            #pragma unroll
            for (int ntp = 0; ntp < 4; ntp++)
                ldm_x4(bb[ntp], sb + OFF_BL + (uint32_t)(b_row + ntp * 16) * PITCH + kB + b_k8);
            #pragma unroll
            for (int mt = 0; mt < 2; mt++)
                #pragma unroll
                for (int nt = 0; nt < 8; nt++)
                    mma16(acc[mt][nt], ah[mt], bb[nt >> 1][(nt & 1) * 2], bb[nt >> 1][(nt & 1) * 2 + 1]);
        }
        __syncthreads();
    }

    // ---------------- epilogue ----------------
    const int rbase = by * MT + wm * 32 + (lane >> 2);
    const int cbase = bx * NTT + wn * 64 + (lane & 3) * 2;
    #pragma unroll
    for (int mt = 0; mt < 2; mt++) {
        #pragma unroll
        for (int h = 0; h < 2; h++) {
            const int r = rbase + mt * 16 + h * 8;
            if (EPI == 0) {
                float* Crow = (float*)C0 + bz * sC + (long long)r * ldc + cbase;
                #pragma unroll
                for (int nt = 0; nt < 8; nt++) {
                    float2 v = make_float2(acc[mt][nt][h * 2], acc[mt][nt][h * 2 + 1]);
                    *reinterpret_cast<float2*>(Crow + nt * 8) = v;
                }
            } else if (EPI == 1) {
                bf16* Ch = (bf16*)C0 + (long long)r * ldc + cbase;
                bf16* Cl = (bf16*)C1 + (long long)r * ldc + cbase;
                #pragma unroll
                for (int nt = 0; nt < 8; nt++) {
                    float v0 = acc[mt][nt][h * 2], v1 = acc[mt][nt][h * 2 + 1];
                    bf16 h0 = __float2bfloat16(v0), h1 = __float2bfloat16(v1);
                    bf16 l0 = __float2bfloat16(v0 - __bfloat162float(h0));
                    bf16 l1 = __float2bfloat16(v1 - __bfloat162float(h1));
                    uint32_t hp = (uint32_t)__bfloat16_as_ushort(h0) | ((uint32_t)__bfloat16_as_ushort(h1) << 16);
                    uint32_t lp = (uint32_t)__bfloat16_as_ushort(l0) | ((uint32_t)__bfloat16_as_ushort(l1) << 16);
                    *reinterpret_cast<uint32_t*>(Ch + nt * 8) = hp;
                    *reinterpret_cast<uint32_t*>(Cl + nt * 8) = lp;
                }
            } else {   // EPI == 2: V transposed hi/lo, batch derived from global row
                const int vb = r >> 11, tok = r & (N_SZ - 1);
                bf16* Th = (bf16*)C0 + (long long)vb * D_SZ * N_SZ + tok;
                bf16* Tl = (bf16*)C1 + (long long)vb * D_SZ * N_SZ + tok;
                #pragma unroll
                for (int nt = 0; nt < 8; nt++)
                    #pragma unroll
                    for (int e = 0; e < 2; e++) {
                        const int col = cbase + nt * 8 + e;
                        float v = acc[mt][nt][h * 2 + e];
                        bf16 hh = __float2bfloat16(v);
                        Th[(long long)col * N_SZ] = hh;
                        Tl[(long long)col * N_SZ] = __float2bfloat16(v - __bfloat162float(hh));
                    }
            }
        }
    }
}

// ---------------- conversions ----------------
__global__ __launch_bounds__(256)
void split_fp32(const float4* __restrict__ in, uint2* __restrict__ hi, uint2* __restrict__ lo, int n4)
{
    int i = blockIdx.x * 256 + threadIdx.x;
    if (i >= n4) return;
    float4 v = in[i];
    bf16 h0 = __float2bfloat16(v.x), h1 = __float2bfloat16(v.y);
    bf16 h2 = __float2bfloat16(v.z), h3 = __float2bfloat16(v.w);
    bf16 l0 = __float2bfloat16(v.x - __bfloat162float(h0));
    bf16 l1 = __float2bfloat16(v.y - __bfloat162float(h1));
    bf16 l2 = __float2bfloat16(v.z - __bfloat162float(h2));
    bf16 l3 = __float2bfloat16(v.w - __bfloat162float(h3));
    uint2 H, L;
    H.x = (uint32_t)__bfloat16_as_ushort(h0) | ((uint32_t)__bfloat16_as_ushort(h1) << 16);
    H.y = (uint32_t)__bfloat16_as_ushort(h2) | ((uint32_t)__bfloat16_as_ushort(h3) << 16);
    L.x = (uint32_t)__bfloat16_as_ushort(l0) | ((uint32_t)__bfloat16_as_ushort(l1) << 16);
    L.y = (uint32_t)__bfloat16_as_ushort(l2) | ((uint32_t)__bfloat16_as_ushort(l3) << 16);
    hi[i] = H; lo[i] = L;
}

// W[d_in, d_out] -> Wt hi/lo [d_out, d_in]
__global__ __launch_bounds__(256)
void transpose_split(const float* __restrict__ W, bf16* __restrict__ Th, bf16* __restrict__ Tl)
{
    __shared__ float t[32][33];
    const int tx = threadIdx.x, ty = threadIdx.y;
    const int c0 = blockIdx.x * 32, r0 = blockIdx.y * 32;
    #pragma unroll
    for (int j = ty; j < 32; j += 8)
        t[j][tx] = W[(long long)(r0 + j) * D_SZ + c0 + tx];
    __syncthreads();
    #pragma unroll
    for (int j = ty; j < 32; j += 8) {
        float v = t[tx][j];                           // = W[r0+tx, c0+j]
        bf16 h = __float2bfloat16(v);
        long long o = (long long)(c0 + j) * D_SZ + r0 + tx;
        Th[o] = h;
        Tl[o] = __float2bfloat16(v - __bfloat162float(h));
    }
}

// ---------------- causal softmax -> bf16 hi/lo P ----------------
__global__ __launch_bounds__(256)
void softmax_split(float* __restrict__ S, bf16* __restrict__ Ph, bf16* __restrict__ Pl,
                   int n, float scale)
{
    const int i = blockIdx.x, b = blockIdx.y;
    const long long base = ((long long)b * n + i) * n;
    float* row = S + base;
    const int L = i + 1;
    const int tid = threadIdx.x;

    __shared__ float red[8];
    __shared__ float bc;

    float m = -3.0e38f;
    for (int j = tid; j < L; j += 256) m = fmaxf(m, row[j] * scale);
    #pragma unroll
    for (int o = 16; o > 0; o >>= 1) m = fmaxf(m, __shfl_xor_sync(0xffffffffu, m, o));
    if ((tid & 31) == 0) red[tid >> 5] = m;
    __syncthreads();
    if (tid < 32) {
        float v = (tid < 8) ? red[tid] : -3.0e38f;
        #pragma unroll
        for (int o = 16; o > 0; o >>= 1) v = fmaxf(v, __shfl_xor_sync(0xffffffffu, v, o));
        if (tid == 0) bc = v;
    }
    __syncthreads();
    m = bc;

    float sum = 0.0f;
    for (int j = tid; j < L; j += 256) {
        float e = __expf(row[j] * scale - m);
        row[j] = e;
        sum += e;
    }
    #pragma unroll
    for (int o = 16; o > 0; o >>= 1) sum += __shfl_xor_sync(0xffffffffu, sum, o);
    __syncthreads();
    if ((tid & 31) == 0) red[tid >> 5] = sum;
    __syncthreads();
    if (tid < 32) {
        float v = (tid < 8) ? red[tid] : 0.0f;
        #pragma unroll
        for (int o = 16; o > 0; o >>= 1) v += __shfl_xor_sync(0xffffffffu, v, o);
        if (tid == 0) bc = v;
    }
    __syncthreads();
    const float inv = 1.0f / bc;

    for (int j = tid; j < n; j += 256) {
        float p = (j < L) ? row[j] * inv : 0.0f;
        bf16 h = __float2bfloat16(p);
        Ph[base + j] = h;
        Pl[base + j] = __float2bfloat16(p - __bfloat162float(h));
    }
}

// ----------------------------------------------------------------------------
extern "C" void kernel_launch(void* const* d_in, const int* in_sizes, int n_in,
                              void* d_out, int out_size)
{
    const float* x  = (const float*)d_in[0];
    const float* Wq = (const float*)d_in[1];
    const float* Wk = (const float*)d_in[2];
    const float* Wv = (const float*)d_in[3];
    float* out = (float*)d_out;

    bf16 *xh, *xl, *Wqh, *Wql, *Wkh, *Wkl, *Wvh, *Wvl;
    bf16 *Qh, *Ql, *Kh, *Kl, *Vth, *Vtl, *Ph, *Pl;
    float* S;
    cudaGetSymbolAddress((void**)&xh, g_xh);   cudaGetSymbolAddress((void**)&xl, g_xl);
    cudaGetSymbolAddress((void**)&Wqh, g_Wqh); cudaGetSymbolAddress((void**)&Wql, g_Wql);
    cudaGetSymbolAddress((void**)&Wkh, g_Wkh); cudaGetSymbolAddress((void**)&Wkl, g_Wkl);
    cudaGetSymbolAddress((void**)&Wvh, g_Wvh); cudaGetSymbolAddress((void**)&Wvl, g_Wvl);
    cudaGetSymbolAddress((void**)&Qh, g_Qh);   cudaGetSymbolAddress((void**)&Ql, g_Ql);
    cudaGetSymbolAddress((void**)&Kh, g_Kh);   cudaGetSymbolAddress((void**)&Kl, g_Kl);
    cudaGetSymbolAddress((void**)&Vth, g_Vth); cudaGetSymbolAddress((void**)&Vtl, g_Vtl);
    cudaGetSymbolAddress((void**)&Ph, g_Ph);   cudaGetSymbolAddress((void**)&Pl, g_Pl);
    cudaGetSymbolAddress((void**)&S, g_S);

    cudaFuncSetAttribute(gemm_mma<0>, cudaFuncAttributeMaxDynamicSharedMemorySize, SMEM_SZ);
    cudaFuncSetAttribute(gemm_mma<1>, cudaFuncAttributeMaxDynamicSharedMemorySize, SMEM_SZ);
    cudaFuncSetAttribute(gemm_mma<2>, cudaFuncAttributeMaxDynamicSharedMemorySize, SMEM_SZ);

    const long long ND = (long long)N_SZ * D_SZ;
    const long long NN = (long long)N_SZ * N_SZ;

    // 1) splits
    split_fp32<<<(B_SZ * N_SZ * D_SZ / 4 + 255) / 256, 256>>>(
        (const float4*)x, (uint2*)xh, (uint2*)xl, B_SZ * N_SZ * D_SZ / 4);
    transpose_split<<<dim3(32, 32), dim3(32, 8)>>>(Wq, Wqh, Wql);
    transpose_split<<<dim3(32, 32), dim3(32, 8)>>>(Wk, Wkh, Wkl);
    transpose_split<<<dim3(32, 32), dim3(32, 8)>>>(Wv, Wvh, Wvl);

    // 2) projections: [8192,1024] = x @ Wt^T
    gemm_mma<1><<<dim3(D_SZ / NTT, B_SZ * N_SZ / MT, 1), NTHREADS, SMEM_SZ>>>(
        xh, xl, Wqh, Wql, Qh, Ql, D_SZ, D_SZ, 0, 0, 0, 0, 0);
    gemm_mma<1><<<dim3(D_SZ / NTT, B_SZ * N_SZ / MT, 1), NTHREADS, SMEM_SZ>>>(
        xh, xl, Wkh, Wkl, Kh, Kl, D_SZ, D_SZ, 0, 0, 0, 0, 0);
    gemm_mma<2><<<dim3(D_SZ / NTT, B_SZ * N_SZ / MT, 1), NTHREADS, SMEM_SZ>>>(
        xh, xl, Wvh, Wvl, Vth, Vtl, D_SZ, 0, 0, 0, 0, 0, 0);

    // 3) S = Q @ K^T (lower-triangle blocks only)
    gemm_mma<0><<<dim3(N_SZ / NTT, N_SZ / MT, B_SZ), NTHREADS, SMEM_SZ>>>(
        Qh, Ql, Kh, Kl, S, nullptr, D_SZ, N_SZ, ND, ND, NN, 1, 0);

    // 4) softmax -> P hi/lo
    softmax_split<<<dim3(N_SZ, B_SZ), 256>>>(S, Ph, Pl, N_SZ, 1.0f / 32.0f);

    // 5) out = P @ V   (B = V^T, K-limited by causality)
    gemm_mma<0><<<dim3(D_SZ / NTT, N_SZ / MT, B_SZ), NTHREADS, SMEM_SZ>>>(
        Ph, Pl, Vth, Vtl, out, nullptr, N_SZ, D_SZ, NN, (long long)D_SZ * N_SZ, ND, 0, 1);
}

// round 6
// speedup vs baseline: 2.8460x; 1.0416x over previous
#include <cuda_runtime.h>
#include <cuda_bf16.h>
#include <cstdint>

// ============================================================================
// CausalAttention b=4, n=2048, d=1024 — mma.sync bf16 split-precision.
// Round-3-proven chassis (256 thr, 128x128 tiles, 2 CTA/SM) + merged QKV
// + PV via ldmatrix.trans on natural-layout V (no V^T scatter).
//   C = Ah@Bh^T + Ah@Bl^T + Al@Bh^T (fp32 accumulate)
// ============================================================================

#define B_SZ 4
#define N_SZ 2048
#define D_SZ 1024
typedef __nv_bfloat16 bf16;

static constexpr long long ND = (long long)N_SZ * D_SZ;
static constexpr long long NN = (long long)N_SZ * N_SZ;

// ---------------- scratch ----------------
__device__ bf16  g_xh [(size_t)B_SZ*N_SZ*D_SZ];
__device__ bf16  g_xl [(size_t)B_SZ*N_SZ*D_SZ];
__device__ bf16  g_Wqh[(size_t)D_SZ*D_SZ];
__device__ bf16  g_Wql[(size_t)D_SZ*D_SZ];
__device__ bf16  g_Wkh[(size_t)D_SZ*D_SZ];
__device__ bf16  g_Wkl[(size_t)D_SZ*D_SZ];
__device__ bf16  g_Wvh[(size_t)D_SZ*D_SZ];
__device__ bf16  g_Wvl[(size_t)D_SZ*D_SZ];
__device__ bf16  g_Qh [(size_t)B_SZ*N_SZ*D_SZ];
__device__ bf16  g_Ql [(size_t)B_SZ*N_SZ*D_SZ];
__device__ bf16  g_Kh [(size_t)B_SZ*N_SZ*D_SZ];
__device__ bf16  g_Kl [(size_t)B_SZ*N_SZ*D_SZ];
__device__ bf16  g_Vh [(size_t)B_SZ*N_SZ*D_SZ];   // natural [n, d] layout
__device__ bf16  g_Vl [(size_t)B_SZ*N_SZ*D_SZ];
__device__ float g_S  [(size_t)B_SZ*N_SZ*N_SZ];
__device__ bf16  g_Ph [(size_t)B_SZ*N_SZ*N_SZ];
__device__ bf16  g_Pl [(size_t)B_SZ*N_SZ*N_SZ];

// ---------------- helpers ----------------
__device__ __forceinline__ uint32_t smem_u32(const void* p) {
    uint32_t a;
    asm("{ .reg .u64 t; cvta.to.shared.u64 t, %1; cvt.u32.u64 %0, t; }" : "=r"(a) : "l"(p));
    return a;
}
__device__ __forceinline__ void cp16(uint32_t dst, const void* src) {
    asm volatile("cp.async.cg.shared.global [%0], [%1], 16;" :: "r"(dst), "l"(src));
}
#define CP_COMMIT() asm volatile("cp.async.commit_group;" ::: "memory")
#define CP_WAIT(n)  asm volatile("cp.async.wait_group %0;" :: "n"(n) : "memory")

__device__ __forceinline__ void ldm_x4(uint32_t* r, uint32_t addr) {
    asm volatile("ldmatrix.sync.aligned.m8n8.x4.shared.b16 {%0,%1,%2,%3}, [%4];"
                 : "=r"(r[0]), "=r"(r[1]), "=r"(r[2]), "=r"(r[3]) : "r"(addr));
}
__device__ __forceinline__ void ldm_x4_t(uint32_t* r, uint32_t addr) {
    asm volatile("ldmatrix.sync.aligned.m8n8.x4.trans.shared.b16 {%0,%1,%2,%3}, [%4];"
                 : "=r"(r[0]), "=r"(r[1]), "=r"(r[2]), "=r"(r[3]) : "r"(addr));
}
__device__ __forceinline__ void mma16(float* c, const uint32_t* a, uint32_t b0, uint32_t b1) {
    asm volatile("mma.sync.aligned.m16n8k16.row.col.f32.bf16.bf16.f32 "
                 "{%0,%1,%2,%3}, {%4,%5,%6,%7}, {%8,%9}, {%0,%1,%2,%3};"
                 : "+f"(c[0]), "+f"(c[1]), "+f"(c[2]), "+f"(c[3])
                 : "r"(a[0]), "r"(a[1]), "r"(a[2]), "r"(a[3]), "r"(b0), "r"(b1));
}

// AB smem: 2 stages x 4 tiles (Ah,Al,Bh,Bl), 128 rows x 80B pitch  (round-3 layout)
static constexpr uint32_t PITCH   = 80;
static constexpr uint32_t TILE_B  = 128 * PITCH;            // 10240
static constexpr uint32_t STAGE_B = 4 * TILE_B;             // 40960
static constexpr uint32_t OFF_AH = 0, OFF_AL = TILE_B, OFF_BH = 2*TILE_B, OFF_BL = 3*TILE_B;
static constexpr uint32_t SMEM_AB = 2 * STAGE_B;            // 81920
// PV smem: P tiles as A above; V tile 32 keys x 272B (128 dims + 16B pad)
static constexpr uint32_t PITCHV = 272;
static constexpr uint32_t V_T    = 32 * PITCHV;             // 8704
static constexpr uint32_t OFF_VH = 2*TILE_B, OFF_VL = 2*TILE_B + V_T;
static constexpr uint32_t STGV   = 2*TILE_B + 2*V_T;        // 37888
static constexpr uint32_t SMEM_PV = 2 * STGV;               // 75776

// ----------------------------------------------------------------------------
// MODE 0: merged QKV. grid (8, 64, 3): bz selects W and destination.
// MODE 1: S = Q@K^T causal. grid (16, 16, 4): bz = batch; skip bx > by.
// 256 threads, 128x128 tile, warp grid 4x2 (warp tile 32x64).
// ----------------------------------------------------------------------------
template <int MODE>
__global__ __launch_bounds__(256, 2)
void gemm_ab(const bf16* __restrict__ Ah_, const bf16* __restrict__ Al_,
             const bf16* __restrict__ B0h, const bf16* __restrict__ B0l,
             const bf16* __restrict__ B1h, const bf16* __restrict__ B1l,
             const bf16* __restrict__ B2h, const bf16* __restrict__ B2l,
             bf16* C0h, bf16* C0l, bf16* C1h, bf16* C1l, bf16* C2h, bf16* C2l,
             float* Sout)
{
    const int bx = blockIdx.x, by = blockIdx.y, bz = blockIdx.z;
    if (MODE == 1 && bx > by) return;

    extern __shared__ char smem[];
    const uint32_t su = smem_u32(smem);
    const int tid = threadIdx.x;
    const int lane = tid & 31, wid = tid >> 5;
    const int wm = wid & 3, wn = wid >> 2;

    const bf16 *pAh, *pAl, *pBh, *pBl;
    if (MODE == 0) {
        pAh = Ah_ + (long long)(by * 128) * 1024;
        pAl = Al_ + (long long)(by * 128) * 1024;
        const bf16* bh = (bz == 0) ? B0h : (bz == 1) ? B1h : B2h;
        const bf16* bl = (bz == 0) ? B0l : (bz == 1) ? B1l : B2l;
        pBh = bh + (long long)(bx * 128) * 1024;
        pBl = bl + (long long)(bx * 128) * 1024;
    } else {
        pAh = Ah_ + bz * ND + (long long)(by * 128) * 1024;
        pAl = Al_ + bz * ND + (long long)(by * 128) * 1024;
        pBh = B0h + bz * ND + (long long)(bx * 128) * 1024;
        pBl = B0l + bz * ND + (long long)(bx * 128) * 1024;
    }

    const int ld_row0 = tid >> 2;          // 0..63
    const int ld_c4   = tid & 3;

    auto load_stage = [&](int stg, int k0) {
        const uint32_t sb = su + stg * STAGE_B;
        #pragma unroll
        for (int it = 0; it < 2; it++) {
            const int row = ld_row0 + it * 64;
            const uint32_t so = (uint32_t)row * PITCH + ld_c4 * 16;
            const long long go = (long long)row * 1024 + k0 + ld_c4 * 8;
            cp16(sb + OFF_AH + so, pAh + go);
            cp16(sb + OFF_AL + so, pAl + go);
            cp16(sb + OFF_BH + so, pBh + go);
            cp16(sb + OFF_BL + so, pBl + go);
        }
    };

    const int a_row = wm * 32 + (lane & 15);
    const int a_k8  = (lane >> 4) * 16;
    const int b_row = wn * 64 + ((lane >> 4) << 3) + (lane & 7);
    const int b_k8  = ((lane >> 3) & 1) * 16;

    float acc[2][8][4] = {};
    const int nchunks = 32;                // K = 1024

    load_stage(0, 0);
    CP_COMMIT();

    for (int i = 0; i < nchunks; i++) {
        if (i + 1 < nchunks) { load_stage((i + 1) & 1, (i + 1) * 32); CP_COMMIT(); CP_WAIT(1); }
        else                 { CP_WAIT(0); }
        __syncthreads();
        const uint32_t sb = su + (i & 1) * STAGE_B;
        #pragma unroll
        for (int ks = 0; ks < 2; ks++) {
            const uint32_t kB = ks * 32;
            uint32_t ah[2][4], al[2][4], bb[4][4];
            #pragma unroll
            for (int mt = 0; mt < 2; mt++) {
                ldm_x4(ah[mt], sb + OFF_AH + (uint32_t)(a_row + mt * 16) * PITCH + kB + a_k8);
                ldm_x4(al[mt], sb + OFF_AL + (uint32_t)(a_row + mt * 16) * PITCH + kB + a_k8);
            }
            #pragma unroll
            for (int ntp = 0; ntp < 4; ntp++)
                ldm_x4(bb[ntp], sb + OFF_BH + (uint32_t)(b_row + ntp * 16) * PITCH + kB + b_k8);
            #pragma unroll
            for (int mt = 0; mt < 2; mt++)
                #pragma unroll
                for (int nt = 0; nt < 8; nt++) {
                    mma16(acc[mt][nt], ah[mt], bb[nt >> 1][(nt & 1) * 2], bb[nt >> 1][(nt & 1) * 2 + 1]);
                    mma16(acc[mt][nt], al[mt], bb[nt >> 1][(nt & 1) * 2], bb[nt >> 1][(nt & 1) * 2 + 1]);
                }
            #pragma unroll
            for (int ntp = 0; ntp < 4; ntp++)
                ldm_x4(bb[ntp], sb + OFF_BL + (uint32_t)(b_row + ntp * 16) * PITCH + kB + b_k8);
            #pragma unroll
            for (int mt = 0; mt < 2; mt++)
                #pragma unroll
                for (int nt = 0; nt < 8; nt++)
                    mma16(acc[mt][nt], ah[mt], bb[nt >> 1][(nt & 1) * 2], bb[nt >> 1][(nt & 1) * 2 + 1]);
        }
        __syncthreads();
    }

    const int rb = by * 128 + wm * 32 + (lane >> 2);
    const int cb = bx * 128 + wn * 64 + (lane & 3) * 2;
    #pragma unroll
    for (int mt = 0; mt < 2; mt++)
        #pragma unroll
        for (int h = 0; h < 2; h++) {
            const int r = rb + mt * 16 + h * 8;
            if (MODE == 1) {
                float* Crow = Sout + bz * NN + (long long)r * N_SZ + cb;
                #pragma unroll
                for (int nt = 0; nt < 8; nt++)
                    *reinterpret_cast<float2*>(Crow + nt * 8) =
                        make_float2(acc[mt][nt][h * 2], acc[mt][nt][h * 2 + 1]);
            } else {
                bf16* Ch = ((bz == 0) ? C0h : (bz == 1) ? C1h : C2h) + (long long)r * 1024 + cb;
                bf16* Cl = ((bz == 0) ? C0l : (bz == 1) ? C1l : C2l) + (long long)r * 1024 + cb;
                #pragma unroll
                for (int nt = 0; nt < 8; nt++) {
                    float v0 = acc[mt][nt][h * 2], v1 = acc[mt][nt][h * 2 + 1];
                    bf16 h0 = __float2bfloat16(v0), h1 = __float2bfloat16(v1);
                    bf16 l0 = __float2bfloat16(v0 - __bfloat162float(h0));
                    bf16 l1 = __float2bfloat16(v1 - __bfloat162float(h1));
                    *reinterpret_cast<uint32_t*>(Ch + nt * 8) =
                        (uint32_t)__bfloat16_as_ushort(h0) | ((uint32_t)__bfloat16_as_ushort(h1) << 16);
                    *reinterpret_cast<uint32_t*>(Cl + nt * 8) =
                        (uint32_t)__bfloat16_as_ushort(l0) | ((uint32_t)__bfloat16_as_ushort(l1) << 16);
                }
            }
        }
}

// ----------------------------------------------------------------------------
// out = P @ V.  P: [n,n] hi/lo (K-major A), V: [n,d] hi/lo consumed via
// ldmatrix.trans. grid (8, 16, 4); K limited to (by+1)*128 by causality.
// ----------------------------------------------------------------------------
__global__ __launch_bounds__(256, 2)
void gemm_pv(const bf16* __restrict__ Ph_, const bf16* __restrict__ Pl_,
             const bf16* __restrict__ Vh_, const bf16* __restrict__ Vl_,
             float* __restrict__ out)
{
    const int bx = blockIdx.x, by = blockIdx.y, bz = blockIdx.z;
    extern __shared__ char smem[];
    const uint32_t su = smem_u32(smem);
    const int tid = threadIdx.x;
    const int lane = tid & 31, wid = tid >> 5;
    const int wm = wid & 3, wn = wid >> 2;

    const bf16* pAh = Ph_ + bz * NN + (long long)(by * 128) * N_SZ;
    const bf16* pAl = Pl_ + bz * NN + (long long)(by * 128) * N_SZ;
    const bf16* pVh = Vh_ + bz * ND + bx * 128;
    const bf16* pVl = Vl_ + bz * ND + bx * 128;

    const int nchunks = (by + 1) * 4;       // keys limit / 32

    const int ld_row0 = tid >> 2, ld_c4 = tid & 3;          // P tiles
    const int lv_row0 = tid >> 4, lv_c16 = tid & 15;        // V tile

    auto load_stage = [&](int stg, int k0) {
        const uint32_t sb = su + stg * STGV;
        #pragma unroll
        for (int it = 0; it < 2; it++) {
            const int row = ld_row0 + it * 64;
            const uint32_t so = (uint32_t)row * PITCH + ld_c4 * 16;
            const long long go = (long long)row * N_SZ + k0 + ld_c4 * 8;
            cp16(sb + OFF_AH + so, pAh + go);
            cp16(sb + OFF_AL + so, pAl + go);
        }
        #pragma unroll
        for (int it = 0; it < 2; it++) {
            const int row = lv_row0 + it * 16;              // key within chunk
            const uint32_t so = (uint32_t)row * PITCHV + lv_c16 * 16;
            const long long go = (long long)(k0 + row) * 1024 + lv_c16 * 8;
            cp16(sb + OFF_VH + so, pVh + go);
            cp16(sb + OFF_VL + so, pVl + go);
        }
    };

    const int a_row = wm * 32 + (lane & 15);
    const int a_k8  = (lane >> 4) * 16;
    // trans-ldmatrix x4 address: matrix index from lane>>3
    const int v_row  = (lane & 7) + ((lane >> 3) & 1) * 8;
    const int v_colB = (wn * 64 + ((lane >> 4) & 1) * 8) * 2;

    float acc[2][8][4] = {};

    load_stage(0, 0);
    CP_COMMIT();

    for (int i = 0; i < nchunks; i++) {
        if (i + 1 < nchunks) { load_stage((i + 1) & 1, (i + 1) * 32); CP_COMMIT(); CP_WAIT(1); }
        else                 { CP_WAIT(0); }
        __syncthreads();
        const uint32_t sb = su + (i & 1) * STGV;
        #pragma unroll
        for (int ks = 0; ks < 2; ks++) {
            const uint32_t kB = ks * 32;
            uint32_t ah[2][4], al[2][4], bb[4][4];
            #pragma unroll
            for (int mt = 0; mt < 2; mt++) {
                ldm_x4(ah[mt], sb + OFF_AH + (uint32_t)(a_row + mt * 16) * PITCH + kB + a_k8);
                ldm_x4(al[mt], sb + OFF_AL + (uint32_t)(a_row + mt * 16) * PITCH + kB + a_k8);
            }
            #pragma unroll
            for (int ntp = 0; ntp < 4; ntp++)
                ldm_x4_t(bb[ntp], sb + OFF_VH + (uint32_t)(ks * 16 + v_row) * PITCHV + v_colB + ntp * 32);
            #pragma unroll
            for (int mt = 0; mt < 2; mt++)
                #pragma unroll
                for (int nt = 0; nt < 8; nt++) {
                    mma16(acc[mt][nt], ah[mt], bb[nt >> 1][(nt & 1) * 2], bb[nt >> 1][(nt & 1) * 2 + 1]);
                    mma16(acc[mt][nt], al[mt], bb[nt >> 1][(nt & 1) * 2], bb[nt >> 1][(nt & 1) * 2 + 1]);
                }
            #pragma unroll
            for (int ntp = 0; ntp < 4; ntp++)
                ldm_x4_t(bb[ntp], sb + OFF_VL + (uint32_t)(ks * 16 + v_row) * PITCHV + v_colB + ntp * 32);
            #pragma unroll
            for (int mt = 0; mt < 2; mt++)
                #pragma unroll
                for (int nt = 0; nt < 8; nt++)
                    mma16(acc[mt][nt], ah[mt], bb[nt >> 1][(nt & 1) * 2], bb[nt >> 1][(nt & 1) * 2 + 1]);
        }
        __syncthreads();
    }

    const int rb = by * 128 + wm * 32 + (lane >> 2);
    const int cb = bx * 128 + wn * 64 + (lane & 3) * 2;
    #pragma unroll
    for (int mt = 0; mt < 2; mt++)
        #pragma unroll
        for (int h = 0; h < 2; h++) {
            const int r = rb + mt * 16 + h * 8;
            float* Crow = out + ((long long)bz * N_SZ + r) * 1024 + cb;
            #pragma unroll
            for (int nt = 0; nt < 8; nt++)
                *reinterpret_cast<float2*>(Crow + nt * 8) =
                    make_float2(acc[mt][nt][h * 2], acc[mt][nt][h * 2 + 1]);
        }
}

// ---------------- conversions ----------------
__global__ __launch_bounds__(256)
void split_fp32(const float4* __restrict__ in, uint2* __restrict__ hi, uint2* __restrict__ lo, int n4)
{
    int i = blockIdx.x * 256 + threadIdx.x;
    if (i >= n4) return;
    float4 v = in[i];
    bf16 h0 = __float2bfloat16(v.x), h1 = __float2bfloat16(v.y);
    bf16 h2 = __float2bfloat16(v.z), h3 = __float2bfloat16(v.w);
    bf16 l0 = __float2bfloat16(v.x - __bfloat162float(h0));
    bf16 l1 = __float2bfloat16(v.y - __bfloat162float(h1));
    bf16 l2 = __float2bfloat16(v.z - __bfloat162float(h2));
    bf16 l3 = __float2bfloat16(v.w - __bfloat162float(h3));
    uint2 H, L;
    H.x = (uint32_t)__bfloat16_as_ushort(h0) | ((uint32_t)__bfloat16_as_ushort(h1) << 16);
    H.y = (uint32_t)__bfloat16_as_ushort(h2) | ((uint32_t)__bfloat16_as_ushort(h3) << 16);
    L.x = (uint32_t)__bfloat16_as_ushort(l0) | ((uint32_t)__bfloat16_as_ushort(l1) << 16);
    L.y = (uint32_t)__bfloat16_as_ushort(l2) | ((uint32_t)__bfloat16_as_ushort(l3) << 16);
    hi[i] = H; lo[i] = L;
}

__global__ __launch_bounds__(256)
void transpose_split(const float* __restrict__ W, bf16* __restrict__ Th, bf16* __restrict__ Tl)
{
    __shared__ float t[32][33];
    const int tx = threadIdx.x, ty = threadIdx.y;
    const int c0 = blockIdx.x * 32, r0 = blockIdx.y * 32;
    #pragma unroll
    for (int j = ty; j < 32; j += 8)
        t[j][tx] = W[(long long)(r0 + j) * D_SZ + c0 + tx];
    __syncthreads();
    #pragma unroll
    for (int j = ty; j < 32; j += 8) {
        float v = t[tx][j];
        bf16 h = __float2bfloat16(v);
        long long o = (long long)(c0 + j) * D_SZ + r0 + tx;
        Th[o] = h;
        Tl[o] = __float2bfloat16(v - __bfloat162float(h));
    }
}

// ---------------- causal softmax -> bf16 hi/lo P ----------------
__global__ __launch_bounds__(256)
void softmax_split(float* __restrict__ S, bf16* __restrict__ Ph, bf16* __restrict__ Pl,
                   int n, float scale)
{
    const int i = blockIdx.x, b = blockIdx.y;
    const long long base = ((long long)b * n + i) * n;
    float* row = S + base;
    const int L = i + 1;
    const int tid = threadIdx.x;

    __shared__ float red[8];
    __shared__ float bc;

    float m = -3.0e38f;
    for (int j = tid; j < L; j += 256) m = fmaxf(m, row[j] * scale);
    #pragma unroll
    for (int o = 16; o > 0; o >>= 1) m = fmaxf(m, __shfl_xor_sync(0xffffffffu, m, o));
    if ((tid & 31) == 0) red[tid >> 5] = m;
    __syncthreads();
    if (tid < 32) {
        float v = (tid < 8) ? red[tid] : -3.0e38f;
        #pragma unroll
        for (int o = 16; o > 0; o >>= 1) v = fmaxf(v, __shfl_xor_sync(0xffffffffu, v, o));
        if (tid == 0) bc = v;
    }
    __syncthreads();
    m = bc;

    float sum = 0.0f;
    for (int j = tid; j < L; j += 256) {
        float e = __expf(row[j] * scale - m);
        row[j] = e;
        sum += e;
    }
    #pragma unroll
    for (int o = 16; o > 0; o >>= 1) sum += __shfl_xor_sync(0xffffffffu, sum, o);
    __syncthreads();
    if ((tid & 31) == 0) red[tid >> 5] = sum;
    __syncthreads();
    if (tid < 32) {
        float v = (tid < 8) ? red[tid] : 0.0f;
        #pragma unroll
        for (int o = 16; o > 0; o >>= 1) v += __shfl_xor_sync(0xffffffffu, v, o);
        if (tid == 0) bc = v;
    }
    __syncthreads();
    const float inv = 1.0f / bc;

    for (int j = tid; j < n; j += 256) {
        float p = (j < L) ? row[j] * inv : 0.0f;
        bf16 h = __float2bfloat16(p);
        Ph[base + j] = h;
        Pl[base + j] = __float2bfloat16(p - __bfloat162float(h));
    }
}

// ----------------------------------------------------------------------------
extern "C" void kernel_launch(void* const* d_in, const int* in_sizes, int n_in,
                              void* d_out, int out_size)
{
    const float* x  = (const float*)d_in[0];
    const float* Wq = (const float*)d_in[1];
    const float* Wk = (const float*)d_in[2];
    const float* Wv = (const float*)d_in[3];
    float* out = (float*)d_out;

    bf16 *xh, *xl, *Wqh, *Wql, *Wkh, *Wkl, *Wvh, *Wvl;
    bf16 *Qh, *Ql, *Kh, *Kl, *Vh, *Vl, *Ph, *Pl;
    float* S;
    cudaGetSymbolAddress((void**)&xh, g_xh);   cudaGetSymbolAddress((void**)&xl, g_xl);
    cudaGetSymbolAddress((void**)&Wqh, g_Wqh); cudaGetSymbolAddress((void**)&Wql, g_Wql);
    cudaGetSymbolAddress((void**)&Wkh, g_Wkh); cudaGetSymbolAddress((void**)&Wkl, g_Wkl);
    cudaGetSymbolAddress((void**)&Wvh, g_Wvh); cudaGetSymbolAddress((void**)&Wvl, g_Wvl);
    cudaGetSymbolAddress((void**)&Qh, g_Qh);   cudaGetSymbolAddress((void**)&Ql, g_Ql);
    cudaGetSymbolAddress((void**)&Kh, g_Kh);   cudaGetSymbolAddress((void**)&Kl, g_Kl);
    cudaGetSymbolAddress((void**)&Vh, g_Vh);   cudaGetSymbolAddress((void**)&Vl, g_Vl);
    cudaGetSymbolAddress((void**)&Ph, g_Ph);   cudaGetSymbolAddress((void**)&Pl, g_Pl);
    cudaGetSymbolAddress((void**)&S, g_S);

    cudaFuncSetAttribute(gemm_ab<0>, cudaFuncAttributeMaxDynamicSharedMemorySize, SMEM_AB);
    cudaFuncSetAttribute(gemm_ab<1>, cudaFuncAttributeMaxDynamicSharedMemorySize, SMEM_AB);
    cudaFuncSetAttribute(gemm_pv,    cudaFuncAttributeMaxDynamicSharedMemorySize, SMEM_PV);

    // 1) splits
    split_fp32<<<(B_SZ * N_SZ * D_SZ / 4 + 255) / 256, 256>>>(
        (const float4*)x, (uint2*)xh, (uint2*)xl, B_SZ * N_SZ * D_SZ / 4);
    transpose_split<<<dim3(32, 32), dim3(32, 8)>>>(Wq, Wqh, Wql);
    transpose_split<<<dim3(32, 32), dim3(32, 8)>>>(Wk, Wkh, Wkl);
    transpose_split<<<dim3(32, 32), dim3(32, 8)>>>(Wv, Wvh, Wvl);

    // 2) merged QKV projection (one launch, 1536 CTAs)
    gemm_ab<0><<<dim3(8, 64, 3), 256, SMEM_AB>>>(
        xh, xl, Wqh, Wql, Wkh, Wkl, Wvh, Wvl,
        Qh, Ql, Kh, Kl, Vh, Vl, nullptr);

    // 3) S = Q @ K^T (lower-triangle blocks only)
    gemm_ab<1><<<dim3(16, 16, 4), 256, SMEM_AB>>>(
        Qh, Ql, Kh, Kl, nullptr, nullptr, nullptr, nullptr,
        nullptr, nullptr, nullptr, nullptr, nullptr, nullptr, S);

    // 4) softmax -> P hi/lo
    softmax_split<<<dim3(N_SZ, B_SZ), 256>>>(S, Ph, Pl, N_SZ, 1.0f / 32.0f);

    // 5) out = P @ V (trans-loaded V, causal K-limit)
    gemm_pv<<<dim3(8, 16, 4), 256, SMEM_PV>>>(Ph, Pl, Vh, Vl, out);
}

// round 7
// speedup vs baseline: 3.0616x; 1.0758x over previous
#include <cuda_runtime.h>
#include <cuda_bf16.h>
#include <cstdint>
#include <cmath>

// ============================================================================
// CausalAttention b=4, n=2048, d=1024 — mma.sync bf16 split-precision.
// R7: PV heavy-first (LPT) scheduling, exact triangular S grid,
//     single-pass register-resident softmax, merged transpose.
//   C = Ah@Bh^T + Ah@Bl^T + Al@Bh^T (fp32 accumulate)
// ============================================================================

#define B_SZ 4
#define N_SZ 2048
#define D_SZ 1024
typedef __nv_bfloat16 bf16;

static constexpr long long ND = (long long)N_SZ * D_SZ;
static constexpr long long NN = (long long)N_SZ * N_SZ;

// ---------------- scratch ----------------
__device__ bf16  g_xh [(size_t)B_SZ*N_SZ*D_SZ];
__device__ bf16  g_xl [(size_t)B_SZ*N_SZ*D_SZ];
__device__ bf16  g_Wqh[(size_t)D_SZ*D_SZ];
__device__ bf16  g_Wql[(size_t)D_SZ*D_SZ];
__device__ bf16  g_Wkh[(size_t)D_SZ*D_SZ];
__device__ bf16  g_Wkl[(size_t)D_SZ*D_SZ];
__device__ bf16  g_Wvh[(size_t)D_SZ*D_SZ];
__device__ bf16  g_Wvl[(size_t)D_SZ*D_SZ];
__device__ bf16  g_Qh [(size_t)B_SZ*N_SZ*D_SZ];
__device__ bf16  g_Ql [(size_t)B_SZ*N_SZ*D_SZ];
__device__ bf16  g_Kh [(size_t)B_SZ*N_SZ*D_SZ];
__device__ bf16  g_Kl [(size_t)B_SZ*N_SZ*D_SZ];
__device__ bf16  g_Vh [(size_t)B_SZ*N_SZ*D_SZ];   // natural [n, d] layout
__device__ bf16  g_Vl [(size_t)B_SZ*N_SZ*D_SZ];
__device__ float g_S  [(size_t)B_SZ*N_SZ*N_SZ];
__device__ bf16  g_Ph [(size_t)B_SZ*N_SZ*N_SZ];
__device__ bf16  g_Pl [(size_t)B_SZ*N_SZ*N_SZ];

// ---------------- helpers ----------------
__device__ __forceinline__ uint32_t smem_u32(const void* p) {
    uint32_t a;
    asm("{ .reg .u64 t; cvta.to.shared.u64 t, %1; cvt.u32.u64 %0, t; }" : "=r"(a) : "l"(p));
    return a;
}
__device__ __forceinline__ void cp16(uint32_t dst, const void* src) {
    asm volatile("cp.async.cg.shared.global [%0], [%1], 16;" :: "r"(dst), "l"(src));
}
#define CP_COMMIT() asm volatile("cp.async.commit_group;" ::: "memory")
#define CP_WAIT(n)  asm volatile("cp.async.wait_group %0;" :: "n"(n) : "memory")

__device__ __forceinline__ void ldm_x4(uint32_t* r, uint32_t addr) {
    asm volatile("ldmatrix.sync.aligned.m8n8.x4.shared.b16 {%0,%1,%2,%3}, [%4];"
                 : "=r"(r[0]), "=r"(r[1]), "=r"(r[2]), "=r"(r[3]) : "r"(addr));
}
__device__ __forceinline__ void ldm_x4_t(uint32_t* r, uint32_t addr) {
    asm volatile("ldmatrix.sync.aligned.m8n8.x4.trans.shared.b16 {%0,%1,%2,%3}, [%4];"
                 : "=r"(r[0]), "=r"(r[1]), "=r"(r[2]), "=r"(r[3]) : "r"(addr));
}
__device__ __forceinline__ void mma16(float* c, const uint32_t* a, uint32_t b0, uint32_t b1) {
    asm volatile("mma.sync.aligned.m16n8k16.row.col.f32.bf16.bf16.f32 "
                 "{%0,%1,%2,%3}, {%4,%5,%6,%7}, {%8,%9}, {%0,%1,%2,%3};"
                 : "+f"(c[0]), "+f"(c[1]), "+f"(c[2]), "+f"(c[3])
                 : "r"(a[0]), "r"(a[1]), "r"(a[2]), "r"(a[3]), "r"(b0), "r"(b1));
}

// AB smem: 2 stages x 4 tiles (Ah,Al,Bh,Bl), 128 rows x 80B pitch
static constexpr uint32_t PITCH   = 80;
static constexpr uint32_t TILE_B  = 128 * PITCH;            // 10240
static constexpr uint32_t STAGE_B = 4 * TILE_B;             // 40960
static constexpr uint32_t OFF_AH = 0, OFF_AL = TILE_B, OFF_BH = 2*TILE_B, OFF_BL = 3*TILE_B;
static constexpr uint32_t SMEM_AB = 2 * STAGE_B;            // 81920
// PV smem: P tiles as A above; V tile 32 keys x 272B
static constexpr uint32_t PITCHV = 272;
static constexpr uint32_t V_T    = 32 * PITCHV;             // 8704
static constexpr uint32_t OFF_VH = 2*TILE_B, OFF_VL = 2*TILE_B + V_T;
static constexpr uint32_t STGV   = 2*TILE_B + 2*V_T;        // 37888
static constexpr uint32_t SMEM_PV = 2 * STGV;               // 75776

// ----------------------------------------------------------------------------
// MODE 0: merged QKV. grid (8, 64, 3): bz selects W and destination.
// MODE 1: S = Q@K^T causal. grid (544,1,1): exact lower-triangle enumeration.
// ----------------------------------------------------------------------------
template <int MODE>
__global__ __launch_bounds__(256, 2)
void gemm_ab(const bf16* __restrict__ Ah_, const bf16* __restrict__ Al_,
             const bf16* __restrict__ B0h, const bf16* __restrict__ B0l,
             const bf16* __restrict__ B1h, const bf16* __restrict__ B1l,
             const bf16* __restrict__ B2h, const bf16* __restrict__ B2l,
             bf16* C0h, bf16* C0l, bf16* C1h, bf16* C1l, bf16* C2h, bf16* C2l,
             float* Sout)
{
    int bx, by, bz;
    if (MODE == 0) {
        bx = blockIdx.x; by = blockIdx.y; bz = blockIdx.z;
    } else {
        // linear -> (batch, lower-triangle tile)
        const int Lb = blockIdx.x;          // 0..543
        bz = Lb & 3;
        const int t = Lb >> 2;              // 0..135
        by = (int)((sqrtf(8.f * (float)t + 1.f) - 1.f) * 0.5f);
        while ((by + 1) * (by + 2) / 2 <= t) by++;
        while (by * (by + 1) / 2 > t) by--;
        bx = t - by * (by + 1) / 2;         // bx <= by guaranteed
    }

    extern __shared__ char smem[];
    const uint32_t su = smem_u32(smem);
    const int tid = threadIdx.x;
    const int lane = tid & 31, wid = tid >> 5;
    const int wm = wid & 3, wn = wid >> 2;

    const bf16 *pAh, *pAl, *pBh, *pBl;
    if (MODE == 0) {
        pAh = Ah_ + (long long)(by * 128) * 1024;
        pAl = Al_ + (long long)(by * 128) * 1024;
        const bf16* bh = (bz == 0) ? B0h : (bz == 1) ? B1h : B2h;
        const bf16* bl = (bz == 0) ? B0l : (bz == 1) ? B1l : B2l;
        pBh = bh + (long long)(bx * 128) * 1024;
        pBl = bl + (long long)(bx * 128) * 1024;
    } else {
        pAh = Ah_ + bz * ND + (long long)(by * 128) * 1024;
        pAl = Al_ + bz * ND + (long long)(by * 128) * 1024;
        pBh = B0h + bz * ND + (long long)(bx * 128) * 1024;
        pBl = B0l + bz * ND + (long long)(bx * 128) * 1024;
    }

    const int ld_row0 = tid >> 2;
    const int ld_c4   = tid & 3;

    auto load_stage = [&](int stg, int k0) {
        const uint32_t sb = su + stg * STAGE_B;
        #pragma unroll
        for (int it = 0; it < 2; it++) {
            const int row = ld_row0 + it * 64;
            const uint32_t so = (uint32_t)row * PITCH + ld_c4 * 16;
            const long long go = (long long)row * 1024 + k0 + ld_c4 * 8;
            cp16(sb + OFF_AH + so, pAh + go);
            cp16(sb + OFF_AL + so, pAl + go);
            cp16(sb + OFF_BH + so, pBh + go);
            cp16(sb + OFF_BL + so, pBl + go);
        }
    };

    const int a_row = wm * 32 + (lane & 15);
    const int a_k8  = (lane >> 4) * 16;
    const int b_row = wn * 64 + ((lane >> 4) << 3) + (lane & 7);
    const int b_k8  = ((lane >> 3) & 1) * 16;

    float acc[2][8][4] = {};
    const int nchunks = 32;

    load_stage(0, 0);
    CP_COMMIT();

    for (int i = 0; i < nchunks; i++) {
        if (i + 1 < nchunks) { load_stage((i + 1) & 1, (i + 1) * 32); CP_COMMIT(); CP_WAIT(1); }
        else                 { CP_WAIT(0); }
        __syncthreads();
        const uint32_t sb = su + (i & 1) * STAGE_B;
        #pragma unroll
        for (int ks = 0; ks < 2; ks++) {
            const uint32_t kB = ks * 32;
            uint32_t ah[2][4], al[2][4], bb[4][4];
            #pragma unroll
            for (int mt = 0; mt < 2; mt++) {
                ldm_x4(ah[mt], sb + OFF_AH + (uint32_t)(a_row + mt * 16) * PITCH + kB + a_k8);
                ldm_x4(al[mt], sb + OFF_AL + (uint32_t)(a_row + mt * 16) * PITCH + kB + a_k8);
            }
            #pragma unroll
            for (int ntp = 0; ntp < 4; ntp++)
                ldm_x4(bb[ntp], sb + OFF_BH + (uint32_t)(b_row + ntp * 16) * PITCH + kB + b_k8);
            #pragma unroll
            for (int mt = 0; mt < 2; mt++)
                #pragma unroll
                for (int nt = 0; nt < 8; nt++) {
                    mma16(acc[mt][nt], ah[mt], bb[nt >> 1][(nt & 1) * 2], bb[nt >> 1][(nt & 1) * 2 + 1]);
                    mma16(acc[mt][nt], al[mt], bb[nt >> 1][(nt & 1) * 2], bb[nt >> 1][(nt & 1) * 2 + 1]);
                }
            #pragma unroll
            for (int ntp = 0; ntp < 4; ntp++)
                ldm_x4(bb[ntp], sb + OFF_BL + (uint32_t)(b_row + ntp * 16) * PITCH + kB + b_k8);
            #pragma unroll
            for (int mt = 0; mt < 2; mt++)
                #pragma unroll
                for (int nt = 0; nt < 8; nt++)
                    mma16(acc[mt][nt], ah[mt], bb[nt >> 1][(nt & 1) * 2], bb[nt >> 1][(nt & 1) * 2 + 1]);
        }
        __syncthreads();
    }

    const int rb = by * 128 + wm * 32 + (lane >> 2);
    const int cb = bx * 128 + wn * 64 + (lane & 3) * 2;
    #pragma unroll
    for (int mt = 0; mt < 2; mt++)
        #pragma unroll
        for (int h = 0; h < 2; h++) {
            const int r = rb + mt * 16 + h * 8;
            if (MODE == 1) {
                float* Crow = Sout + bz * NN + (long long)r * N_SZ + cb;
                #pragma unroll
                for (int nt = 0; nt < 8; nt++)
                    *reinterpret_cast<float2*>(Crow + nt * 8) =
                        make_float2(acc[mt][nt][h * 2], acc[mt][nt][h * 2 + 1]);
            } else {
                bf16* Ch = ((bz == 0) ? C0h : (bz == 1) ? C1h : C2h) + (long long)r * 1024 + cb;
                bf16* Cl = ((bz == 0) ? C0l : (bz == 1) ? C1l : C2l) + (long long)r * 1024 + cb;
                #pragma unroll
                for (int nt = 0; nt < 8; nt++) {
                    float v0 = acc[mt][nt][h * 2], v1 = acc[mt][nt][h * 2 + 1];
                    bf16 h0 = __float2bfloat16(v0), h1 = __float2bfloat16(v1);
                    bf16 l0 = __float2bfloat16(v0 - __bfloat162float(h0));
                    bf16 l1 = __float2bfloat16(v1 - __bfloat162float(h1));
                    *reinterpret_cast<uint32_t*>(Ch + nt * 8) =
                        (uint32_t)__bfloat16_as_ushort(h0) | ((uint32_t)__bfloat16_as_ushort(h1) << 16);
                    *reinterpret_cast<uint32_t*>(Cl + nt * 8) =
                        (uint32_t)__bfloat16_as_ushort(l0) | ((uint32_t)__bfloat16_as_ushort(l1) << 16);
                }
            }
        }
}

// ----------------------------------------------------------------------------
// out = P @ V. grid (512,1,1), heavy-first (descending by) LPT ordering.
// K limited to (by+1)*128 by causality.
// ----------------------------------------------------------------------------
__global__ __launch_bounds__(256, 2)
void gemm_pv(const bf16* __restrict__ Ph_, const bf16* __restrict__ Pl_,
             const bf16* __restrict__ Vh_, const bf16* __restrict__ Vl_,
             float* __restrict__ out)
{
    // heavy-first remap: by descends with linear bid so wave-1 gets the
    // longest tiles and work-stealing backfills with light ones (LPT).
    const int Lb = blockIdx.x;              // 0..511
    const int by = 15 - (Lb >> 5);
    const int rr = Lb & 31;
    const int bx = rr & 7, bz = rr >> 3;

    extern __shared__ char smem[];
    const uint32_t su = smem_u32(smem);
    const int tid = threadIdx.x;
    const int lane = tid & 31, wid = tid >> 5;
    const int wm = wid & 3, wn = wid >> 2;

    const bf16* pAh = Ph_ + bz * NN + (long long)(by * 128) * N_SZ;
    const bf16* pAl = Pl_ + bz * NN + (long long)(by * 128) * N_SZ;
    const bf16* pVh = Vh_ + bz * ND + bx * 128;
    const bf16* pVl = Vl_ + bz * ND + bx * 128;

    const int nchunks = (by + 1) * 4;

    const int ld_row0 = tid >> 2, ld_c4 = tid & 3;
    const int lv_row0 = tid >> 4, lv_c16 = tid & 15;

    auto load_stage = [&](int stg, int k0) {
        const uint32_t sb = su + stg * STGV;
        #pragma unroll
        for (int it = 0; it < 2; it++) {
            const int row = ld_row0 + it * 64;
            const uint32_t so = (uint32_t)row * PITCH + ld_c4 * 16;
            const long long go = (long long)row * N_SZ + k0 + ld_c4 * 8;
            cp16(sb + OFF_AH + so, pAh + go);
            cp16(sb + OFF_AL + so, pAl + go);
        }
        #pragma unroll
        for (int it = 0; it < 2; it++) {
            const int row = lv_row0 + it * 16;
            const uint32_t so = (uint32_t)row * PITCHV + lv_c16 * 16;
            const long long go = (long long)(k0 + row) * 1024 + lv_c16 * 8;
            cp16(sb + OFF_VH + so, pVh + go);
            cp16(sb + OFF_VL + so, pVl + go);
        }
    };

    const int a_row = wm * 32 + (lane & 15);
    const int a_k8  = (lane >> 4) * 16;
    const int v_row  = (lane & 7) + ((lane >> 3) & 1) * 8;
    const int v_colB = (wn * 64 + ((lane >> 4) & 1) * 8) * 2;

    float acc[2][8][4] = {};

    load_stage(0, 0);
    CP_COMMIT();

    for (int i = 0; i < nchunks; i++) {
        if (i + 1 < nchunks) { load_stage((i + 1) & 1, (i + 1) * 32); CP_COMMIT(); CP_WAIT(1); }
        else                 { CP_WAIT(0); }
        __syncthreads();
        const uint32_t sb = su + (i & 1) * STGV;
        #pragma unroll
        for (int ks = 0; ks < 2; ks++) {
            const uint32_t kB = ks * 32;
            uint32_t ah[2][4], al[2][4], bb[4][4];
            #pragma unroll
            for (int mt = 0; mt < 2; mt++) {
                ldm_x4(ah[mt], sb + OFF_AH + (uint32_t)(a_row + mt * 16) * PITCH + kB + a_k8);
                ldm_x4(al[mt], sb + OFF_AL + (uint32_t)(a_row + mt * 16) * PITCH + kB + a_k8);
            }
            #pragma unroll
            for (int ntp = 0; ntp < 4; ntp++)
                ldm_x4_t(bb[ntp], sb + OFF_VH + (uint32_t)(ks * 16 + v_row) * PITCHV + v_colB + ntp * 32);
            #pragma unroll
            for (int mt = 0; mt < 2; mt++)
                #pragma unroll
                for (int nt = 0; nt < 8; nt++) {
                    mma16(acc[mt][nt], ah[mt], bb[nt >> 1][(nt & 1) * 2], bb[nt >> 1][(nt & 1) * 2 + 1]);
                    mma16(acc[mt][nt], al[mt], bb[nt >> 1][(nt & 1) * 2], bb[nt >> 1][(nt & 1) * 2 + 1]);
                }
            #pragma unroll
            for (int ntp = 0; ntp < 4; ntp++)
                ldm_x4_t(bb[ntp], sb + OFF_VL + (uint32_t)(ks * 16 + v_row) * PITCHV + v_colB + ntp * 32);
            #pragma unroll
            for (int mt = 0; mt < 2; mt++)
                #pragma unroll
                for (int nt = 0; nt < 8; nt++)
                    mma16(acc[mt][nt], ah[mt], bb[nt >> 1][(nt & 1) * 2], bb[nt >> 1][(nt & 1) * 2 + 1]);
        }
        __syncthreads();
    }

    const int rb = by * 128 + wm * 32 + (lane >> 2);
    const int cb = bx * 128 + wn * 64 + (lane & 3) * 2;
    #pragma unroll
    for (int mt = 0; mt < 2; mt++)
        #pragma unroll
        for (int h = 0; h < 2; h++) {
            const int r = rb + mt * 16 + h * 8;
            float* Crow = out + ((long long)bz * N_SZ + r) * 1024 + cb;
            #pragma unroll
            for (int nt = 0; nt < 8; nt++)
                *reinterpret_cast<float2*>(Crow + nt * 8) =
                    make_float2(acc[mt][nt][h * 2], acc[mt][nt][h * 2 + 1]);
        }
}

// ---------------- conversions ----------------
__global__ __launch_bounds__(256)
void split_fp32(const float4* __restrict__ in, uint2* __restrict__ hi, uint2* __restrict__ lo, int n4)
{
    int i = blockIdx.x * 256 + threadIdx.x;
    if (i >= n4) return;
    float4 v = in[i];
    bf16 h0 = __float2bfloat16(v.x), h1 = __float2bfloat16(v.y);
    bf16 h2 = __float2bfloat16(v.z), h3 = __float2bfloat16(v.w);
    bf16 l0 = __float2bfloat16(v.x - __bfloat162float(h0));
    bf16 l1 = __float2bfloat16(v.y - __bfloat162float(h1));
    bf16 l2 = __float2bfloat16(v.z - __bfloat162float(h2));
    bf16 l3 = __float2bfloat16(v.w - __bfloat162float(h3));
    uint2 H, L;
    H.x = (uint32_t)__bfloat16_as_ushort(h0) | ((uint32_t)__bfloat16_as_ushort(h1) << 16);
    H.y = (uint32_t)__bfloat16_as_ushort(h2) | ((uint32_t)__bfloat16_as_ushort(h3) << 16);
    L.x = (uint32_t)__bfloat16_as_ushort(l0) | ((uint32_t)__bfloat16_as_ushort(l1) << 16);
    L.y = (uint32_t)__bfloat16_as_ushort(l2) | ((uint32_t)__bfloat16_as_ushort(l3) << 16);
    hi[i] = H; lo[i] = L;
}

// merged: z selects Wq/Wk/Wv
__global__ __launch_bounds__(256)
void transpose_split3(const float* __restrict__ W0, const float* __restrict__ W1,
                      const float* __restrict__ W2,
                      bf16* __restrict__ T0h, bf16* __restrict__ T0l,
                      bf16* __restrict__ T1h, bf16* __restrict__ T1l,
                      bf16* __restrict__ T2h, bf16* __restrict__ T2l)
{
    const int z = blockIdx.z;
    const float* W = (z == 0) ? W0 : (z == 1) ? W1 : W2;
    bf16* Th = (z == 0) ? T0h : (z == 1) ? T1h : T2h;
    bf16* Tl = (z == 0) ? T0l : (z == 1) ? T1l : T2l;

    __shared__ float t[32][33];
    const int tx = threadIdx.x, ty = threadIdx.y;
    const int c0 = blockIdx.x * 32, r0 = blockIdx.y * 32;
    #pragma unroll
    for (int j = ty; j < 32; j += 8)
        t[j][tx] = W[(long long)(r0 + j) * D_SZ + c0 + tx];
    __syncthreads();
    #pragma unroll
    for (int j = ty; j < 32; j += 8) {
        float v = t[tx][j];
        bf16 h = __float2bfloat16(v);
        long long o = (long long)(c0 + j) * D_SZ + r0 + tx;
        Th[o] = h;
        Tl[o] = __float2bfloat16(v - __bfloat162float(h));
    }
}

// ---------------- single-pass causal softmax -> bf16 hi/lo P ----------------
// Row register-resident: one read of S, one write of P (clipped at the 128-
// block boundary Lw = ceil128(i+1), which is exactly PV's causal K-limit).
__global__ __launch_bounds__(256)
void softmax_split(const float* __restrict__ S, bf16* __restrict__ Ph, bf16* __restrict__ Pl,
                   int n, float scale)
{
    const int i = blockIdx.x, b = blockIdx.y;
    const long long base = ((long long)b * n + i) * n;
    const float* row = S + base;
    const int L  = i + 1;
    const int Lw = ((i >> 7) + 1) << 7;     // PV reads exactly [0, Lw)
    const int tid = threadIdx.x;

    __shared__ float red[8];
    __shared__ float bc;

    float v[8];
    float m = -3.0e38f;
    #pragma unroll
    for (int k = 0; k < 8; k++) {
        const int j = tid + k * 256;
        float s = (j < L) ? row[j] * scale : -3.0e38f;
        v[k] = s;
        m = fmaxf(m, s);
    }
    #pragma unroll
    for (int o = 16; o > 0; o >>= 1) m = fmaxf(m, __shfl_xor_sync(0xffffffffu, m, o));
    if ((tid & 31) == 0) red[tid >> 5] = m;
    __syncthreads();
    if (tid < 32) {
        float t = (tid < 8) ? red[tid] : -3.0e38f;
        #pragma unroll
        for (int o = 16; o > 0; o >>= 1) t = fmaxf(t, __shfl_xor_sync(0xffffffffu, t, o));
        if (tid == 0) bc = t;
    }
    __syncthreads();
    m = bc;

    float sum = 0.0f;
    #pragma unroll
    for (int k = 0; k < 8; k++) {
        float e = __expf(v[k] - m);         // exp(-3e38 - m) == 0 for masked
        v[k] = e;
        sum += e;
    }
    #pragma unroll
    for (int o = 16; o > 0; o >>= 1) sum += __shfl_xor_sync(0xffffffffu, sum, o);
    __syncthreads();
    if ((tid & 31) == 0) red[tid >> 5] = sum;
    __syncthreads();
    if (tid < 32) {
        float t = (tid < 8) ? red[tid] : 0.0f;
        #pragma unroll
        for (int o = 16; o > 0; o >>= 1) t += __shfl_xor_sync(0xffffffffu, t, o);
        if (tid == 0) bc = t;
    }
    __syncthreads();
    const float inv = 1.0f / bc;

    #pragma unroll
    for (int k = 0; k < 8; k++) {
        const int j = tid + k * 256;
        if (j < Lw) {
            float p = v[k] * inv;           // masked entries: v[k]==0 -> p==0
            bf16 h = __float2bfloat16(p);
            Ph[base + j] = h;
            Pl[base + j] = __float2bfloat16(p - __bfloat162float(h));
        }
    }
}

// ----------------------------------------------------------------------------
extern "C" void kernel_launch(void* const* d_in, const int* in_sizes, int n_in,
                              void* d_out, int out_size)
{
    const float* x  = (const float*)d_in[0];
    const float* Wq = (const float*)d_in[1];
    const float* Wk = (const float*)d_in[2];
    const float* Wv = (const float*)d_in[3];
    float* out = (float*)d_out;

    bf16 *xh, *xl, *Wqh, *Wql, *Wkh, *Wkl, *Wvh, *Wvl;
    bf16 *Qh, *Ql, *Kh, *Kl, *Vh, *Vl, *Ph, *Pl;
    float* S;
    cudaGetSymbolAddress((void**)&xh, g_xh);   cudaGetSymbolAddress((void**)&xl, g_xl);
    cudaGetSymbolAddress((void**)&Wqh, g_Wqh); cudaGetSymbolAddress((void**)&Wql, g_Wql);
    cudaGetSymbolAddress((void**)&Wkh, g_Wkh); cudaGetSymbolAddress((void**)&Wkl, g_Wkl);
    cudaGetSymbolAddress((void**)&Wvh, g_Wvh); cudaGetSymbolAddress((void**)&Wvl, g_Wvl);
    cudaGetSymbolAddress((void**)&Qh, g_Qh);   cudaGetSymbolAddress((void**)&Ql, g_Ql);
    cudaGetSymbolAddress((void**)&Kh, g_Kh);   cudaGetSymbolAddress((void**)&Kl, g_Kl);
    cudaGetSymbolAddress((void**)&Vh, g_Vh);   cudaGetSymbolAddress((void**)&Vl, g_Vl);
    cudaGetSymbolAddress((void**)&Ph, g_Ph);   cudaGetSymbolAddress((void**)&Pl, g_Pl);
    cudaGetSymbolAddress((void**)&S, g_S);

    cudaFuncSetAttribute(gemm_ab<0>, cudaFuncAttributeMaxDynamicSharedMemorySize, SMEM_AB);
    cudaFuncSetAttribute(gemm_ab<1>, cudaFuncAttributeMaxDynamicSharedMemorySize, SMEM_AB);
    cudaFuncSetAttribute(gemm_pv,    cudaFuncAttributeMaxDynamicSharedMemorySize, SMEM_PV);

    // 1) splits
    split_fp32<<<(B_SZ * N_SZ * D_SZ / 4 + 255) / 256, 256>>>(
        (const float4*)x, (uint2*)xh, (uint2*)xl, B_SZ * N_SZ * D_SZ / 4);
    transpose_split3<<<dim3(32, 32, 3), dim3(32, 8)>>>(
        Wq, Wk, Wv, Wqh, Wql, Wkh, Wkl, Wvh, Wvl);

    // 2) merged QKV projection
    gemm_ab<0><<<dim3(8, 64, 3), 256, SMEM_AB>>>(
        xh, xl, Wqh, Wql, Wkh, Wkl, Wvh, Wvl,
        Qh, Ql, Kh, Kl, Vh, Vl, nullptr);

    // 3) S = Q @ K^T — exact triangular grid, no null CTAs
    gemm_ab<1><<<dim3(544, 1, 1), 256, SMEM_AB>>>(
        Qh, Ql, Kh, Kl, nullptr, nullptr, nullptr, nullptr,
        nullptr, nullptr, nullptr, nullptr, nullptr, nullptr, S);

    // 4) single-pass softmax -> P hi/lo (writes clipped to PV's read window)
    softmax_split<<<dim3(N_SZ, B_SZ), 256>>>(S, Ph, Pl, N_SZ, 1.0f / 32.0f);

    // 5) out = P @ V — heavy-first LPT ordering
    gemm_pv<<<dim3(512, 1, 1), 256, SMEM_PV>>>(Ph, Pl, Vh, Vl, out);
}

// round 8
// speedup vs baseline: 3.6396x; 1.1888x over previous
#include <cuda_runtime.h>
#include <cuda_bf16.h>
#include <cstdint>
#include <cmath>

// ============================================================================
// CausalAttention b=4, n=2048, d=1024 — mma.sync bf16 split-precision.
// R8: XOR-swizzled smem (no pad), 3-stage cp.async pipeline, single barrier
//     per K-chunk. Scheduling from R7 (LPT PV, triangular S grid) retained.
//   C = Ah@Bh^T + Ah@Bl^T + Al@Bh^T (fp32 accumulate)
// ============================================================================

#define B_SZ 4
#define N_SZ 2048
#define D_SZ 1024
typedef __nv_bfloat16 bf16;

static constexpr long long ND = (long long)N_SZ * D_SZ;
static constexpr long long NN = (long long)N_SZ * N_SZ;

// ---------------- scratch ----------------
__device__ bf16  g_xh [(size_t)B_SZ*N_SZ*D_SZ];
__device__ bf16  g_xl [(size_t)B_SZ*N_SZ*D_SZ];
__device__ bf16  g_Wqh[(size_t)D_SZ*D_SZ];
__device__ bf16  g_Wql[(size_t)D_SZ*D_SZ];
__device__ bf16  g_Wkh[(size_t)D_SZ*D_SZ];
__device__ bf16  g_Wkl[(size_t)D_SZ*D_SZ];
__device__ bf16  g_Wvh[(size_t)D_SZ*D_SZ];
__device__ bf16  g_Wvl[(size_t)D_SZ*D_SZ];
__device__ bf16  g_Qh [(size_t)B_SZ*N_SZ*D_SZ];
__device__ bf16  g_Ql [(size_t)B_SZ*N_SZ*D_SZ];
__device__ bf16  g_Kh [(size_t)B_SZ*N_SZ*D_SZ];
__device__ bf16  g_Kl [(size_t)B_SZ*N_SZ*D_SZ];
__device__ bf16  g_Vh [(size_t)B_SZ*N_SZ*D_SZ];
__device__ bf16  g_Vl [(size_t)B_SZ*N_SZ*D_SZ];
__device__ float g_S  [(size_t)B_SZ*N_SZ*N_SZ];
__device__ bf16  g_Ph [(size_t)B_SZ*N_SZ*N_SZ];
__device__ bf16  g_Pl [(size_t)B_SZ*N_SZ*N_SZ];

// ---------------- helpers ----------------
__device__ __forceinline__ uint32_t smem_u32(const void* p) {
    uint32_t a;
    asm("{ .reg .u64 t; cvta.to.shared.u64 t, %1; cvt.u32.u64 %0, t; }" : "=r"(a) : "l"(p));
    return a;
}
__device__ __forceinline__ void cp16(uint32_t dst, const void* src) {
    asm volatile("cp.async.cg.shared.global [%0], [%1], 16;" :: "r"(dst), "l"(src));
}
#define CP_COMMIT() asm volatile("cp.async.commit_group;" ::: "memory")
#define CP_WAIT(n)  asm volatile("cp.async.wait_group %0;" :: "n"(n) : "memory")

__device__ __forceinline__ void ldm_x4(uint32_t* r, uint32_t addr) {
    asm volatile("ldmatrix.sync.aligned.m8n8.x4.shared.b16 {%0,%1,%2,%3}, [%4];"
                 : "=r"(r[0]), "=r"(r[1]), "=r"(r[2]), "=r"(r[3]) : "r"(addr));
}
__device__ __forceinline__ void ldm_x4_t(uint32_t* r, uint32_t addr) {
    asm volatile("ldmatrix.sync.aligned.m8n8.x4.trans.shared.b16 {%0,%1,%2,%3}, [%4];"
                 : "=r"(r[0]), "=r"(r[1]), "=r"(r[2]), "=r"(r[3]) : "r"(addr));
}
__device__ __forceinline__ void mma16(float* c, const uint32_t* a, uint32_t b0, uint32_t b1) {
    asm volatile("mma.sync.aligned.m16n8k16.row.col.f32.bf16.bf16.f32 "
                 "{%0,%1,%2,%3}, {%4,%5,%6,%7}, {%8,%9}, {%0,%1,%2,%3};"
                 : "+f"(c[0]), "+f"(c[1]), "+f"(c[2]), "+f"(c[3])
                 : "r"(a[0]), "r"(a[1]), "r"(a[2]), "r"(a[3]), "r"(b0), "r"(b1));
}

// XOR swizzles (pad-free, conflict-free for cp.async stores + 8-lane ldsm phases)
__device__ __forceinline__ uint32_t swAB(int row, int c16) {   // 128 rows x 64B
    return (uint32_t)row * 64 + (uint32_t)((c16 ^ ((row >> 1) & 3)) << 4);
}
__device__ __forceinline__ uint32_t swV(int row, int c16) {    // 32 rows x 256B
    return (uint32_t)row * 256 + (uint32_t)((c16 ^ (row & 7)) << 4);
}

// AB smem: 3 stages x 4 tiles (Ah,Al,Bh,Bl), 128 rows x 64B swizzled
static constexpr uint32_t TILE_B  = 128 * 64;               // 8192
static constexpr uint32_t STAGE_B = 4 * TILE_B;             // 32768
static constexpr uint32_t OFF_AH = 0, OFF_AL = TILE_B, OFF_BH = 2*TILE_B, OFF_BL = 3*TILE_B;
static constexpr uint32_t SMEM_AB = 3 * STAGE_B;            // 98304
// PV smem: P hi/lo tiles (as A) + V hi/lo tiles 32 rows x 256B swizzled
static constexpr uint32_t V_T  = 32 * 256;                  // 8192
static constexpr uint32_t OFF_VH = 2*TILE_B, OFF_VL = 2*TILE_B + V_T;
static constexpr uint32_t STGV = 2*TILE_B + 2*V_T;          // 32768
static constexpr uint32_t SMEM_PV = 3 * STGV;               // 98304

// ----------------------------------------------------------------------------
// MODE 0: merged QKV. grid (8, 64, 3). MODE 1: S = Q@K^T. grid (544,1,1).
// ----------------------------------------------------------------------------
template <int MODE>
__global__ __launch_bounds__(256, 2)
void gemm_ab(const bf16* __restrict__ Ah_, const bf16* __restrict__ Al_,
             const bf16* __restrict__ B0h, const bf16* __restrict__ B0l,
             const bf16* __restrict__ B1h, const bf16* __restrict__ B1l,
             const bf16* __restrict__ B2h, const bf16* __restrict__ B2l,
             bf16* C0h, bf16* C0l, bf16* C1h, bf16* C1l, bf16* C2h, bf16* C2l,
             float* Sout)
{
    int bx, by, bz;
    if (MODE == 0) {
        bx = blockIdx.x; by = blockIdx.y; bz = blockIdx.z;
    } else {
        const int Lb = blockIdx.x;
        bz = Lb & 3;
        const int t = Lb >> 2;
        by = (int)((sqrtf(8.f * (float)t + 1.f) - 1.f) * 0.5f);
        while ((by + 1) * (by + 2) / 2 <= t) by++;
        while (by * (by + 1) / 2 > t) by--;
        bx = t - by * (by + 1) / 2;
    }

    extern __shared__ char smem[];
    const uint32_t su = smem_u32(smem);
    const int tid = threadIdx.x;
    const int lane = tid & 31, wid = tid >> 5;
    const int wm = wid & 3, wn = wid >> 2;

    const bf16 *pAh, *pAl, *pBh, *pBl;
    if (MODE == 0) {
        pAh = Ah_ + (long long)(by * 128) * 1024;
        pAl = Al_ + (long long)(by * 128) * 1024;
        const bf16* bh = (bz == 0) ? B0h : (bz == 1) ? B1h : B2h;
        const bf16* bl = (bz == 0) ? B0l : (bz == 1) ? B1l : B2l;
        pBh = bh + (long long)(bx * 128) * 1024;
        pBl = bl + (long long)(bx * 128) * 1024;
    } else {
        pAh = Ah_ + bz * ND + (long long)(by * 128) * 1024;
        pAl = Al_ + bz * ND + (long long)(by * 128) * 1024;
        pBh = B0h + bz * ND + (long long)(bx * 128) * 1024;
        pBl = B0l + bz * ND + (long long)(bx * 128) * 1024;
    }

    auto load_stage = [&](int stg, int k0) {
        const uint32_t sb = su + (uint32_t)stg * STAGE_B;
        #pragma unroll
        for (int it = 0; it < 2; it++) {
            const int ch = tid + it * 256;           // 0..511
            const int row = ch >> 2, c = ch & 3;
            const uint32_t so = swAB(row, c);
            const long long go = (long long)row * 1024 + k0 + c * 8;
            cp16(sb + OFF_AH + so, pAh + go);
            cp16(sb + OFF_AL + so, pAl + go);
            cp16(sb + OFF_BH + so, pBh + go);
            cp16(sb + OFF_BL + so, pBl + go);
        }
    };

    const int a_row = wm * 32 + (lane & 15);
    const int a_c16 = lane >> 4;                     // 0/1
    const int b_row = wn * 64 + ((lane >> 4) << 3) + (lane & 7);
    const int b_c16 = (lane >> 3) & 1;

    float acc[2][8][4] = {};
    const int nchunks = 32;

    load_stage(0, 0);  CP_COMMIT();
    load_stage(1, 32); CP_COMMIT();
    int ld_stg = 2;

    for (int i = 0; i < nchunks; i++) {
        if (i + 1 < nchunks) { CP_WAIT(1); } else { CP_WAIT(0); }
        __syncthreads();     // publishes stage i; protects stage (i+2)%3 from reload
        if (i + 2 < nchunks) {
            load_stage(ld_stg, (i + 2) * 32); CP_COMMIT();
            ld_stg = (ld_stg == 2) ? 0 : ld_stg + 1;
        }
        const uint32_t sb = su + (uint32_t)(i % 3) * STAGE_B;
        #pragma unroll
        for (int ks = 0; ks < 2; ks++) {
            const int ca = ks * 2 + a_c16;
            const int cbv = ks * 2 + b_c16;
            uint32_t ah[2][4], al[2][4], bb[4][4];
            #pragma unroll
            for (int mt = 0; mt < 2; mt++) {
                ldm_x4(ah[mt], sb + OFF_AH + swAB(a_row + mt * 16, ca));
                ldm_x4(al[mt], sb + OFF_AL + swAB(a_row + mt * 16, ca));
            }
            #pragma unroll
            for (int ntp = 0; ntp < 4; ntp++)
                ldm_x4(bb[ntp], sb + OFF_BH + swAB(b_row + ntp * 16, cbv));
            #pragma unroll
            for (int mt = 0; mt < 2; mt++)
                #pragma unroll
                for (int nt = 0; nt < 8; nt++) {
                    mma16(acc[mt][nt], ah[mt], bb[nt >> 1][(nt & 1) * 2], bb[nt >> 1][(nt & 1) * 2 + 1]);
                    mma16(acc[mt][nt], al[mt], bb[nt >> 1][(nt & 1) * 2], bb[nt >> 1][(nt & 1) * 2 + 1]);
                }
            #pragma unroll
            for (int ntp = 0; ntp < 4; ntp++)
                ldm_x4(bb[ntp], sb + OFF_BL + swAB(b_row + ntp * 16, cbv));
            #pragma unroll
            for (int mt = 0; mt < 2; mt++)
                #pragma unroll
                for (int nt = 0; nt < 8; nt++)
                    mma16(acc[mt][nt], ah[mt], bb[nt >> 1][(nt & 1) * 2], bb[nt >> 1][(nt & 1) * 2 + 1]);
        }
    }
    __syncthreads();

    const int rb = by * 128 + wm * 32 + (lane >> 2);
    const int cb = bx * 128 + wn * 64 + (lane & 3) * 2;
    #pragma unroll
    for (int mt = 0; mt < 2; mt++)
        #pragma unroll
        for (int h = 0; h < 2; h++) {
            const int r = rb + mt * 16 + h * 8;
            if (MODE == 1) {
                float* Crow = Sout + bz * NN + (long long)r * N_SZ + cb;
                #pragma unroll
                for (int nt = 0; nt < 8; nt++)
                    *reinterpret_cast<float2*>(Crow + nt * 8) =
                        make_float2(acc[mt][nt][h * 2], acc[mt][nt][h * 2 + 1]);
            } else {
                bf16* Ch = ((bz == 0) ? C0h : (bz == 1) ? C1h : C2h) + (long long)r * 1024 + cb;
                bf16* Cl = ((bz == 0) ? C0l : (bz == 1) ? C1l : C2l) + (long long)r * 1024 + cb;
                #pragma unroll
                for (int nt = 0; nt < 8; nt++) {
                    float v0 = acc[mt][nt][h * 2], v1 = acc[mt][nt][h * 2 + 1];
                    bf16 h0 = __float2bfloat16(v0), h1 = __float2bfloat16(v1);
                    bf16 l0 = __float2bfloat16(v0 - __bfloat162float(h0));
                    bf16 l1 = __float2bfloat16(v1 - __bfloat162float(h1));
                    *reinterpret_cast<uint32_t*>(Ch + nt * 8) =
                        (uint32_t)__bfloat16_as_ushort(h0) | ((uint32_t)__bfloat16_as_ushort(h1) << 16);
                    *reinterpret_cast<uint32_t*>(Cl + nt * 8) =
                        (uint32_t)__bfloat16_as_ushort(l0) | ((uint32_t)__bfloat16_as_ushort(l1) << 16);
                }
            }
        }
}

// ----------------------------------------------------------------------------
// out = P @ V. grid (512,1,1), heavy-first LPT; K limit (by+1)*128.
// ----------------------------------------------------------------------------
__global__ __launch_bounds__(256, 2)
void gemm_pv(const bf16* __restrict__ Ph_, const bf16* __restrict__ Pl_,
             const bf16* __restrict__ Vh_, const bf16* __restrict__ Vl_,
             float* __restrict__ out)
{
    const int Lb = blockIdx.x;
    const int by = 15 - (Lb >> 5);
    const int rr = Lb & 31;
    const int bx = rr & 7, bz = rr >> 3;

    extern __shared__ char smem[];
    const uint32_t su = smem_u32(smem);
    const int tid = threadIdx.x;
    const int lane = tid & 31, wid = tid >> 5;
    const int wm = wid & 3, wn = wid >> 2;

    const bf16* pAh = Ph_ + bz * NN + (long long)(by * 128) * N_SZ;
    const bf16* pAl = Pl_ + bz * NN + (long long)(by * 128) * N_SZ;
    const bf16* pVh = Vh_ + bz * ND + bx * 128;
    const bf16* pVl = Vl_ + bz * ND + bx * 128;

    const int nchunks = (by + 1) * 4;        // >= 4

    auto load_stage = [&](int stg, int k0) {
        const uint32_t sb = su + (uint32_t)stg * STGV;
        #pragma unroll
        for (int it = 0; it < 2; it++) {     // P tiles: 512 chunks each
            const int ch = tid + it * 256;
            const int row = ch >> 2, c = ch & 3;
            const uint32_t so = swAB(row, c);
            const long long go = (long long)row * N_SZ + k0 + c * 8;
            cp16(sb + OFF_AH + so, pAh + go);
            cp16(sb + OFF_AL + so, pAl + go);
        }
        #pragma unroll
        for (int it = 0; it < 2; it++) {     // V tiles: 32 rows x 16 c16
            const int ch = tid + it * 256;
            const int row = ch >> 4, c = ch & 15;
            const uint32_t so = swV(row, c);
            const long long go = (long long)(k0 + row) * 1024 + c * 8;
            cp16(sb + OFF_VH + so, pVh + go);
            cp16(sb + OFF_VL + so, pVl + go);
        }
    };

    const int a_row = wm * 32 + (lane & 15);
    const int a_c16 = lane >> 4;
    const int v_row  = (lane & 7) + ((lane >> 3) & 1) * 8;      // 0..15
    const int v_c16b = wn * 8 + ((lane >> 4) & 1);              // base c16 in V row

    float acc[2][8][4] = {};

    load_stage(0, 0);  CP_COMMIT();
    load_stage(1, 32); CP_COMMIT();
    int ld_stg = 2;

    for (int i = 0; i < nchunks; i++) {
        if (i + 1 < nchunks) { CP_WAIT(1); } else { CP_WAIT(0); }
        __syncthreads();
        if (i + 2 < nchunks) {
            load_stage(ld_stg, (i + 2) * 32); CP_COMMIT();
            ld_stg = (ld_stg == 2) ? 0 : ld_stg + 1;
        }
        const uint32_t sb = su + (uint32_t)(i % 3) * STGV;
        #pragma unroll
        for (int ks = 0; ks < 2; ks++) {
            const int ca = ks * 2 + a_c16;
            const int vr = ks * 16 + v_row;
            uint32_t ah[2][4], al[2][4], bb[4][4];
            #pragma unroll
            for (int mt = 0; mt < 2; mt++) {
                ldm_x4(ah[mt], sb + OFF_AH + swAB(a_row + mt * 16, ca));
                ldm_x4(al[mt], sb + OFF_AL + swAB(a_row + mt * 16, ca));
            }
            #pragma unroll
            for (int ntp = 0; ntp < 4; ntp++)
                ldm_x4_t(bb[ntp], sb + OFF_VH + swV(vr, v_c16b + ntp * 2));
            #pragma unroll
            for (int mt = 0; mt < 2; mt++)
                #pragma unroll
                for (int nt = 0; nt < 8; nt++) {
                    mma16(acc[mt][nt], ah[mt], bb[nt >> 1][(nt & 1) * 2], bb[nt >> 1][(nt & 1) * 2 + 1]);
                    mma16(acc[mt][nt], al[mt], bb[nt >> 1][(nt & 1) * 2], bb[nt >> 1][(nt & 1) * 2 + 1]);
                }
            #pragma unroll
            for (int ntp = 0; ntp < 4; ntp++)
                ldm_x4_t(bb[ntp], sb + OFF_VL + swV(vr, v_c16b + ntp * 2));
            #pragma unroll
            for (int mt = 0; mt < 2; mt++)
                #pragma unroll
                for (int nt = 0; nt < 8; nt++)
                    mma16(acc[mt][nt], ah[mt], bb[nt >> 1][(nt & 1) * 2], bb[nt >> 1][(nt & 1) * 2 + 1]);
        }
    }
    __syncthreads();

    const int rb = by * 128 + wm * 32 + (lane >> 2);
    const int cb = bx * 128 + wn * 64 + (lane & 3) * 2;
    #pragma unroll
    for (int mt = 0; mt < 2; mt++)
        #pragma unroll
        for (int h = 0; h < 2; h++) {
            const int r = rb + mt * 16 + h * 8;
            float* Crow = out + ((long long)bz * N_SZ + r) * 1024 + cb;
            #pragma unroll
            for (int nt = 0; nt < 8; nt++)
                *reinterpret_cast<float2*>(Crow + nt * 8) =
                    make_float2(acc[mt][nt][h * 2], acc[mt][nt][h * 2 + 1]);
        }
}

// ---------------- conversions ----------------
__global__ __launch_bounds__(256)
void split_fp32(const float4* __restrict__ in, uint2* __restrict__ hi, uint2* __restrict__ lo, int n4)
{
    int i = blockIdx.x * 256 + threadIdx.x;
    if (i >= n4) return;
    float4 v = in[i];
    bf16 h0 = __float2bfloat16(v.x), h1 = __float2bfloat16(v.y);
    bf16 h2 = __float2bfloat16(v.z), h3 = __float2bfloat16(v.w);
    bf16 l0 = __float2bfloat16(v.x - __bfloat162float(h0));
    bf16 l1 = __float2bfloat16(v.y - __bfloat162float(h1));
    bf16 l2 = __float2bfloat16(v.z - __bfloat162float(h2));
    bf16 l3 = __float2bfloat16(v.w - __bfloat162float(h3));
    uint2 H, L;
    H.x = (uint32_t)__bfloat16_as_ushort(h0) | ((uint32_t)__bfloat16_as_ushort(h1) << 16);
    H.y = (uint32_t)__bfloat16_as_ushort(h2) | ((uint32_t)__bfloat16_as_ushort(h3) << 16);
    L.x = (uint32_t)__bfloat16_as_ushort(l0) | ((uint32_t)__bfloat16_as_ushort(l1) << 16);
    L.y = (uint32_t)__bfloat16_as_ushort(l2) | ((uint32_t)__bfloat16_as_ushort(l3) << 16);
    hi[i] = H; lo[i] = L;
}

__global__ __launch_bounds__(256)
void transpose_split3(const float* __restrict__ W0, const float* __restrict__ W1,
                      const float* __restrict__ W2,
                      bf16* __restrict__ T0h, bf16* __restrict__ T0l,
                      bf16* __restrict__ T1h, bf16* __restrict__ T1l,
                      bf16* __restrict__ T2h, bf16* __restrict__ T2l)
{
    const int z = blockIdx.z;
    const float* W = (z == 0) ? W0 : (z == 1) ? W1 : W2;
    bf16* Th = (z == 0) ? T0h : (z == 1) ? T1h : T2h;
    bf16* Tl = (z == 0) ? T0l : (z == 1) ? T1l : T2l;

    __shared__ float t[32][33];
    const int tx = threadIdx.x, ty = threadIdx.y;
    const int c0 = blockIdx.x * 32, r0 = blockIdx.y * 32;
    #pragma unroll
    for (int j = ty; j < 32; j += 8)
        t[j][tx] = W[(long long)(r0 + j) * D_SZ + c0 + tx];
    __syncthreads();
    #pragma unroll
    for (int j = ty; j < 32; j += 8) {
        float v = t[tx][j];
        bf16 h = __float2bfloat16(v);
        long long o = (long long)(c0 + j) * D_SZ + r0 + tx;
        Th[o] = h;
        Tl[o] = __float2bfloat16(v - __bfloat162float(h));
    }
}

// ---------------- single-pass causal softmax -> bf16 hi/lo P ----------------
__global__ __launch_bounds__(256)
void softmax_split(const float* __restrict__ S, bf16* __restrict__ Ph, bf16* __restrict__ Pl,
                   int n, float scale)
{
    const int i = blockIdx.x, b = blockIdx.y;
    const long long base = ((long long)b * n + i) * n;
    const float* row = S + base;
    const int L  = i + 1;
    const int Lw = ((i >> 7) + 1) << 7;
    const int tid = threadIdx.x;

    __shared__ float red[8];
    __shared__ float bc;

    float v[8];
    float m = -3.0e38f;
    #pragma unroll
    for (int k = 0; k < 8; k++) {
        const int j = tid + k * 256;
        float s = (j < L) ? row[j] * scale : -3.0e38f;
        v[k] = s;
        m = fmaxf(m, s);
    }
    #pragma unroll
    for (int o = 16; o > 0; o >>= 1) m = fmaxf(m, __shfl_xor_sync(0xffffffffu, m, o));
    if ((tid & 31) == 0) red[tid >> 5] = m;
    __syncthreads();
    if (tid < 32) {
        float t = (tid < 8) ? red[tid] : -3.0e38f;
        #pragma unroll
        for (int o = 16; o > 0; o >>= 1) t = fmaxf(t, __shfl_xor_sync(0xffffffffu, t, o));
        if (tid == 0) bc = t;
    }
    __syncthreads();
    m = bc;

    float sum = 0.0f;
    #pragma unroll
    for (int k = 0; k < 8; k++) {
        float e = __expf(v[k] - m);
        v[k] = e;
        sum += e;
    }
    #pragma unroll
    for (int o = 16; o > 0; o >>= 1) sum += __shfl_xor_sync(0xffffffffu, sum, o);
    __syncthreads();
    if ((tid & 31) == 0) red[tid >> 5] = sum;
    __syncthreads();
    if (tid < 32) {
        float t = (tid < 8) ? red[tid] : 0.0f;
        #pragma unroll
        for (int o = 16; o > 0; o >>= 1) t += __shfl_xor_sync(0xffffffffu, t, o);
        if (tid == 0) bc = t;
    }
    __syncthreads();
    const float inv = 1.0f / bc;

    #pragma unroll
    for (int k = 0; k < 8; k++) {
        const int j = tid + k * 256;
        if (j < Lw) {
            float p = v[k] * inv;
            bf16 h = __float2bfloat16(p);
            Ph[base + j] = h;
            Pl[base + j] = __float2bfloat16(p - __bfloat162float(h));
        }
    }
}

// ----------------------------------------------------------------------------
extern "C" void kernel_launch(void* const* d_in, const int* in_sizes, int n_in,
                              void* d_out, int out_size)
{
    const float* x  = (const float*)d_in[0];
    const float* Wq = (const float*)d_in[1];
    const float* Wk = (const float*)d_in[2];
    const float* Wv = (const float*)d_in[3];
    float* out = (float*)d_out;

    bf16 *xh, *xl, *Wqh, *Wql, *Wkh, *Wkl, *Wvh, *Wvl;
    bf16 *Qh, *Ql, *Kh, *Kl, *Vh, *Vl, *Ph, *Pl;
    float* S;
    cudaGetSymbolAddress((void**)&xh, g_xh);   cudaGetSymbolAddress((void**)&xl, g_xl);
    cudaGetSymbolAddress((void**)&Wqh, g_Wqh); cudaGetSymbolAddress((void**)&Wql, g_Wql);
    cudaGetSymbolAddress((void**)&Wkh, g_Wkh); cudaGetSymbolAddress((void**)&Wkl, g_Wkl);
    cudaGetSymbolAddress((void**)&Wvh, g_Wvh); cudaGetSymbolAddress((void**)&Wvl, g_Wvl);
    cudaGetSymbolAddress((void**)&Qh, g_Qh);   cudaGetSymbolAddress((void**)&Ql, g_Ql);
    cudaGetSymbolAddress((void**)&Kh, g_Kh);   cudaGetSymbolAddress((void**)&Kl, g_Kl);
    cudaGetSymbolAddress((void**)&Vh, g_Vh);   cudaGetSymbolAddress((void**)&Vl, g_Vl);
    cudaGetSymbolAddress((void**)&Ph, g_Ph);   cudaGetSymbolAddress((void**)&Pl, g_Pl);
    cudaGetSymbolAddress((void**)&S, g_S);

    cudaFuncSetAttribute(gemm_ab<0>, cudaFuncAttributeMaxDynamicSharedMemorySize, SMEM_AB);
    cudaFuncSetAttribute(gemm_ab<1>, cudaFuncAttributeMaxDynamicSharedMemorySize, SMEM_AB);
    cudaFuncSetAttribute(gemm_pv,    cudaFuncAttributeMaxDynamicSharedMemorySize, SMEM_PV);

    split_fp32<<<(B_SZ * N_SZ * D_SZ / 4 + 255) / 256, 256>>>(
        (const float4*)x, (uint2*)xh, (uint2*)xl, B_SZ * N_SZ * D_SZ / 4);
    transpose_split3<<<dim3(32, 32, 3), dim3(32, 8)>>>(
        Wq, Wk, Wv, Wqh, Wql, Wkh, Wkl, Wvh, Wvl);

    gemm_ab<0><<<dim3(8, 64, 3), 256, SMEM_AB>>>(
        xh, xl, Wqh, Wql, Wkh, Wkl, Wvh, Wvl,
        Qh, Ql, Kh, Kl, Vh, Vl, nullptr);

    gemm_ab<1><<<dim3(544, 1, 1), 256, SMEM_AB>>>(
        Qh, Ql, Kh, Kl, nullptr, nullptr, nullptr, nullptr,
        nullptr, nullptr, nullptr, nullptr, nullptr, nullptr, S);

    softmax_split<<<dim3(N_SZ, B_SZ), 256>>>(S, Ph, Pl, N_SZ, 1.0f / 32.0f);

    gemm_pv<<<dim3(512, 1, 1), 256, SMEM_PV>>>(Ph, Pl, Vh, Vl, out);
}

// round 9
// speedup vs baseline: 3.6501x; 1.0029x over previous
#include <cuda_runtime.h>
#include <cuda_bf16.h>
#include <cstdint>
#include <cmath>

// ============================================================================
// CausalAttention b=4, n=2048, d=1024 — mma.sync bf16 split-precision.
// R9: warp-parity ks stagger (cover ldsm windows) + merged S/V-proj launch
//     (tail-fill). R8 chassis: XOR swizzle, 3-stage cp.async, 1 barrier/chunk.
// ============================================================================

#define B_SZ 4
#define N_SZ 2048
#define D_SZ 1024
typedef __nv_bfloat16 bf16;

static constexpr long long ND = (long long)N_SZ * D_SZ;
static constexpr long long NN = (long long)N_SZ * N_SZ;

// ---------------- scratch ----------------
__device__ bf16  g_xh [(size_t)B_SZ*N_SZ*D_SZ];
__device__ bf16  g_xl [(size_t)B_SZ*N_SZ*D_SZ];
__device__ bf16  g_Wqh[(size_t)D_SZ*D_SZ];
__device__ bf16  g_Wql[(size_t)D_SZ*D_SZ];
__device__ bf16  g_Wkh[(size_t)D_SZ*D_SZ];
__device__ bf16  g_Wkl[(size_t)D_SZ*D_SZ];
__device__ bf16  g_Wvh[(size_t)D_SZ*D_SZ];
__device__ bf16  g_Wvl[(size_t)D_SZ*D_SZ];
__device__ bf16  g_Qh [(size_t)B_SZ*N_SZ*D_SZ];
__device__ bf16  g_Ql [(size_t)B_SZ*N_SZ*D_SZ];
__device__ bf16  g_Kh [(size_t)B_SZ*N_SZ*D_SZ];
__device__ bf16  g_Kl [(size_t)B_SZ*N_SZ*D_SZ];
__device__ bf16  g_Vh [(size_t)B_SZ*N_SZ*D_SZ];
__device__ bf16  g_Vl [(size_t)B_SZ*N_SZ*D_SZ];
__device__ float g_S  [(size_t)B_SZ*N_SZ*N_SZ];
__device__ bf16  g_Ph [(size_t)B_SZ*N_SZ*N_SZ];
__device__ bf16  g_Pl [(size_t)B_SZ*N_SZ*N_SZ];

// ---------------- helpers ----------------
__device__ __forceinline__ uint32_t smem_u32(const void* p) {
    uint32_t a;
    asm("{ .reg .u64 t; cvta.to.shared.u64 t, %1; cvt.u32.u64 %0, t; }" : "=r"(a) : "l"(p));
    return a;
}
__device__ __forceinline__ void cp16(uint32_t dst, const void* src) {
    asm volatile("cp.async.cg.shared.global [%0], [%1], 16;" :: "r"(dst), "l"(src));
}
#define CP_COMMIT() asm volatile("cp.async.commit_group;" ::: "memory")
#define CP_WAIT(n)  asm volatile("cp.async.wait_group %0;" :: "n"(n) : "memory")

__device__ __forceinline__ void ldm_x4(uint32_t* r, uint32_t addr) {
    asm volatile("ldmatrix.sync.aligned.m8n8.x4.shared.b16 {%0,%1,%2,%3}, [%4];"
                 : "=r"(r[0]), "=r"(r[1]), "=r"(r[2]), "=r"(r[3]) : "r"(addr));
}
__device__ __forceinline__ void ldm_x4_t(uint32_t* r, uint32_t addr) {
    asm volatile("ldmatrix.sync.aligned.m8n8.x4.trans.shared.b16 {%0,%1,%2,%3}, [%4];"
                 : "=r"(r[0]), "=r"(r[1]), "=r"(r[2]), "=r"(r[3]) : "r"(addr));
}
__device__ __forceinline__ void mma16(float* c, const uint32_t* a, uint32_t b0, uint32_t b1) {
    asm volatile("mma.sync.aligned.m16n8k16.row.col.f32.bf16.bf16.f32 "
                 "{%0,%1,%2,%3}, {%4,%5,%6,%7}, {%8,%9}, {%0,%1,%2,%3};"
                 : "+f"(c[0]), "+f"(c[1]), "+f"(c[2]), "+f"(c[3])
                 : "r"(a[0]), "r"(a[1]), "r"(a[2]), "r"(a[3]), "r"(b0), "r"(b1));
}

// XOR swizzles (pad-free, conflict-free for cp.async stores + ldsm phases)
__device__ __forceinline__ uint32_t swAB(int row, int c16) {   // 128 rows x 64B
    return (uint32_t)row * 64 + (uint32_t)((c16 ^ ((row >> 1) & 3)) << 4);
}
__device__ __forceinline__ uint32_t swV(int row, int c16) {    // 32 rows x 256B
    return (uint32_t)row * 256 + (uint32_t)((c16 ^ (row & 7)) << 4);
}

static constexpr uint32_t TILE_B  = 128 * 64;               // 8192
static constexpr uint32_t STAGE_B = 4 * TILE_B;             // 32768
static constexpr uint32_t OFF_AH = 0, OFF_AL = TILE_B, OFF_BH = 2*TILE_B, OFF_BL = 3*TILE_B;
static constexpr uint32_t SMEM_AB = 3 * STAGE_B;            // 98304
static constexpr uint32_t V_T  = 32 * 256;                  // 8192
static constexpr uint32_t OFF_VH = 2*TILE_B, OFF_VL = 2*TILE_B + V_T;
static constexpr uint32_t STGV = 2*TILE_B + 2*V_T;          // 32768
static constexpr uint32_t SMEM_PV = 3 * STGV;               // 98304

// ----------------------------------------------------------------------------
// MODE 0: QK projection. grid (8, 64, 2): bz selects Wq/Wk -> Q/K.
// MODE 1: merged S + V-proj. grid (1056,1,1):
//   Lb <  544 : S = Q@K^T lower-triangle tile (fp32 out)
//   Lb >= 544 : V-projection tile (bf16 hi/lo out)
// Param map (MODE1): Ah_=Qh Al_=Ql B0=Kh/Kl B1=xh/xl B2=Wvh/Wvl C0=Vh/Vl Sout=S
// ----------------------------------------------------------------------------
template <int MODE>
__global__ __launch_bounds__(256, 2)
void gemm_ab(const bf16* __restrict__ Ah_, const bf16* __restrict__ Al_,
             const bf16* __restrict__ B0h, const bf16* __restrict__ B0l,
             const bf16* __restrict__ B1h, const bf16* __restrict__ B1l,
             const bf16* __restrict__ B2h, const bf16* __restrict__ B2l,
             bf16* C0h, bf16* C0l, bf16* C1h, bf16* C1l,
             float* Sout)
{
    int bx, by, bz;
    bool isS = false;
    if (MODE == 0) {
        bx = blockIdx.x; by = blockIdx.y; bz = blockIdx.z;
    } else {
        const int Lb = blockIdx.x;
        if (Lb < 544) {
            isS = true;
            bz = Lb & 3;
            const int t = Lb >> 2;
            by = (int)((sqrtf(8.f * (float)t + 1.f) - 1.f) * 0.5f);
            while ((by + 1) * (by + 2) / 2 <= t) by++;
            while (by * (by + 1) / 2 > t) by--;
            bx = t - by * (by + 1) / 2;
        } else {
            const int t2 = Lb - 544;          // V-projection tile
            bx = t2 & 7; by = t2 >> 3; bz = 0;
        }
    }

    extern __shared__ char smem[];
    const uint32_t su = smem_u32(smem);
    const int tid = threadIdx.x;
    const int lane = tid & 31, wid = tid >> 5;
    const int wm = wid & 3, wn = wid >> 2;

    const bf16 *pAh, *pAl, *pBh, *pBl;
    if (MODE == 0) {
        pAh = Ah_ + (long long)(by * 128) * 1024;
        pAl = Al_ + (long long)(by * 128) * 1024;
        const bf16* bh = (bz == 0) ? B0h : B1h;
        const bf16* bl = (bz == 0) ? B0l : B1l;
        pBh = bh + (long long)(bx * 128) * 1024;
        pBl = bl + (long long)(bx * 128) * 1024;
    } else if (isS) {
        pAh = Ah_ + bz * ND + (long long)(by * 128) * 1024;
        pAl = Al_ + bz * ND + (long long)(by * 128) * 1024;
        pBh = B0h + bz * ND + (long long)(bx * 128) * 1024;
        pBl = B0l + bz * ND + (long long)(bx * 128) * 1024;
    } else {                                  // V-proj: A = x, B = Wv
        pAh = B1h + (long long)(by * 128) * 1024;
        pAl = B1l + (long long)(by * 128) * 1024;
        pBh = B2h + (long long)(bx * 128) * 1024;
        pBl = B2l + (long long)(bx * 128) * 1024;
    }

    auto load_stage = [&](int stg, int k0) {
        const uint32_t sb = su + (uint32_t)stg * STAGE_B;
        #pragma unroll
        for (int it = 0; it < 2; it++) {
            const int ch = tid + it * 256;
            const int row = ch >> 2, c = ch & 3;
            const uint32_t so = swAB(row, c);
            const long long go = (long long)row * 1024 + k0 + c * 8;
            cp16(sb + OFF_AH + so, pAh + go);
            cp16(sb + OFF_AL + so, pAl + go);
            cp16(sb + OFF_BH + so, pBh + go);
            cp16(sb + OFF_BL + so, pBl + go);
        }
    };

    const int a_row = wm * 32 + (lane & 15);
    const int a_c16 = lane >> 4;
    const int b_row = wn * 64 + ((lane >> 4) << 3) + (lane & 7);
    const int b_c16 = (lane >> 3) & 1;
    const int kpar  = wid & 1;                // warp-parity ks stagger

    float acc[2][8][4] = {};
    const int nchunks = 32;

    load_stage(0, 0);  CP_COMMIT();
    load_stage(1, 32); CP_COMMIT();
    int ld_stg = 2;

    for (int i = 0; i < nchunks; i++) {
        if (i + 1 < nchunks) { CP_WAIT(1); } else { CP_WAIT(0); }
        __syncthreads();
        if (i + 2 < nchunks) {
            load_stage(ld_stg, (i + 2) * 32); CP_COMMIT();
            ld_stg = (ld_stg == 2) ? 0 : ld_stg + 1;
        }
        const uint32_t sb = su + (uint32_t)(i % 3) * STAGE_B;
        #pragma unroll
        for (int ksi = 0; ksi < 2; ksi++) {
            const int ks = ksi ^ kpar;
            const int ca = ks * 2 + a_c16;
            const int cbv = ks * 2 + b_c16;
            uint32_t ah[2][4], al[2][4], bb[4][4];
            #pragma unroll
            for (int mt = 0; mt < 2; mt++) {
                ldm_x4(ah[mt], sb + OFF_AH + swAB(a_row + mt * 16, ca));
                ldm_x4(al[mt], sb + OFF_AL + swAB(a_row + mt * 16, ca));
            }
            #pragma unroll
            for (int ntp = 0; ntp < 4; ntp++)
                ldm_x4(bb[ntp], sb + OFF_BH + swAB(b_row + ntp * 16, cbv));
            #pragma unroll
            for (int mt = 0; mt < 2; mt++)
                #pragma unroll
                for (int nt = 0; nt < 8; nt++) {
                    mma16(acc[mt][nt], ah[mt], bb[nt >> 1][(nt & 1) * 2], bb[nt >> 1][(nt & 1) * 2 + 1]);
                    mma16(acc[mt][nt], al[mt], bb[nt >> 1][(nt & 1) * 2], bb[nt >> 1][(nt & 1) * 2 + 1]);
                }
            #pragma unroll
            for (int ntp = 0; ntp < 4; ntp++)
                ldm_x4(bb[ntp], sb + OFF_BL + swAB(b_row + ntp * 16, cbv));
            #pragma unroll
            for (int mt = 0; mt < 2; mt++)
                #pragma unroll
                for (int nt = 0; nt < 8; nt++)
                    mma16(acc[mt][nt], ah[mt], bb[nt >> 1][(nt & 1) * 2], bb[nt >> 1][(nt & 1) * 2 + 1]);
        }
    }
    __syncthreads();

    const int rb = by * 128 + wm * 32 + (lane >> 2);
    const int cb = bx * 128 + wn * 64 + (lane & 3) * 2;
    #pragma unroll
    for (int mt = 0; mt < 2; mt++)
        #pragma unroll
        for (int h = 0; h < 2; h++) {
            const int r = rb + mt * 16 + h * 8;
            if (MODE == 1 && isS) {
                float* Crow = Sout + bz * NN + (long long)r * N_SZ + cb;
                #pragma unroll
                for (int nt = 0; nt < 8; nt++)
                    *reinterpret_cast<float2*>(Crow + nt * 8) =
                        make_float2(acc[mt][nt][h * 2], acc[mt][nt][h * 2 + 1]);
            } else {
                bf16 *Ch, *Cl;
                if (MODE == 0) {
                    Ch = ((bz == 0) ? C0h : C1h) + (long long)r * 1024 + cb;
                    Cl = ((bz == 0) ? C0l : C1l) + (long long)r * 1024 + cb;
                } else {                       // V-proj output
                    Ch = C0h + (long long)r * 1024 + cb;
                    Cl = C0l + (long long)r * 1024 + cb;
                }
                #pragma unroll
                for (int nt = 0; nt < 8; nt++) {
                    float v0 = acc[mt][nt][h * 2], v1 = acc[mt][nt][h * 2 + 1];
                    bf16 h0 = __float2bfloat16(v0), h1 = __float2bfloat16(v1);
                    bf16 l0 = __float2bfloat16(v0 - __bfloat162float(h0));
                    bf16 l1 = __float2bfloat16(v1 - __bfloat162float(h1));
                    *reinterpret_cast<uint32_t*>(Ch + nt * 8) =
                        (uint32_t)__bfloat16_as_ushort(h0) | ((uint32_t)__bfloat16_as_ushort(h1) << 16);
                    *reinterpret_cast<uint32_t*>(Cl + nt * 8) =
                        (uint32_t)__bfloat16_as_ushort(l0) | ((uint32_t)__bfloat16_as_ushort(l1) << 16);
                }
            }
        }
}

// ----------------------------------------------------------------------------
// out = P @ V. grid (512,1,1), heavy-first LPT; K limit (by+1)*128.
// ----------------------------------------------------------------------------
__global__ __launch_bounds__(256, 2)
void gemm_pv(const bf16* __restrict__ Ph_, const bf16* __restrict__ Pl_,
             const bf16* __restrict__ Vh_, const bf16* __restrict__ Vl_,
             float* __restrict__ out)
{
    const int Lb = blockIdx.x;
    const int by = 15 - (Lb >> 5);
    const int rr = Lb & 31;
    const int bx = rr & 7, bz = rr >> 3;

    extern __shared__ char smem[];
    const uint32_t su = smem_u32(smem);
    const int tid = threadIdx.x;
    const int lane = tid & 31, wid = tid >> 5;
    const int wm = wid & 3, wn = wid >> 2;

    const bf16* pAh = Ph_ + bz * NN + (long long)(by * 128) * N_SZ;
    const bf16* pAl = Pl_ + bz * NN + (long long)(by * 128) * N_SZ;
    const bf16* pVh = Vh_ + bz * ND + bx * 128;
    const bf16* pVl = Vl_ + bz * ND + bx * 128;

    const int nchunks = (by + 1) * 4;

    auto load_stage = [&](int stg, int k0) {
        const uint32_t sb = su + (uint32_t)stg * STGV;
        #pragma unroll
        for (int it = 0; it < 2; it++) {
            const int ch = tid + it * 256;
            const int row = ch >> 2, c = ch & 3;
            const uint32_t so = swAB(row, c);
            const long long go = (long long)row * N_SZ + k0 + c * 8;
            cp16(sb + OFF_AH + so, pAh + go);
            cp16(sb + OFF_AL + so, pAl + go);
        }
        #pragma unroll
        for (int it = 0; it < 2; it++) {
            const int ch = tid + it * 256;
            const int row = ch >> 4, c = ch & 15;
            const uint32_t so = swV(row, c);
            const long long go = (long long)(k0 + row) * 1024 + c * 8;
            cp16(sb + OFF_VH + so, pVh + go);
            cp16(sb + OFF_VL + so, pVl + go);
        }
    };

    const int a_row = wm * 32 + (lane & 15);
    const int a_c16 = lane >> 4;
    const int v_row  = (lane & 7) + ((lane >> 3) & 1) * 8;
    const int v_c16b = wn * 8 + ((lane >> 4) & 1);
    const int kpar = wid & 1;

    float acc[2][8][4] = {};

    load_stage(0, 0);  CP_COMMIT();
    load_stage(1, 32); CP_COMMIT();
    int ld_stg = 2;

    for (int i = 0; i < nchunks; i++) {
        if (i + 1 < nchunks) { CP_WAIT(1); } else { CP_WAIT(0); }
        __syncthreads();
        if (i + 2 < nchunks) {
            load_stage(ld_stg, (i + 2) * 32); CP_COMMIT();
            ld_stg = (ld_stg == 2) ? 0 : ld_stg + 1;
        }
        const uint32_t sb = su + (uint32_t)(i % 3) * STGV;
        #pragma unroll
        for (int ksi = 0; ksi < 2; ksi++) {
            const int ks = ksi ^ kpar;
            const int ca = ks * 2 + a_c16;
            const int vr = ks * 16 + v_row;
            uint32_t ah[2][4], al[2][4], bb[4][4];
            #pragma unroll
            for (int mt = 0; mt < 2; mt++) {
                ldm_x4(ah[mt], sb + OFF_AH + swAB(a_row + mt * 16, ca));
                ldm_x4(al[mt], sb + OFF_AL + swAB(a_row + mt * 16, ca));
            }
            #pragma unroll
            for (int ntp = 0; ntp < 4; ntp++)
                ldm_x4_t(bb[ntp], sb + OFF_VH + swV(vr, v_c16b + ntp * 2));
            #pragma unroll
            for (int mt = 0; mt < 2; mt++)
                #pragma unroll
                for (int nt = 0; nt < 8; nt++) {
                    mma16(acc[mt][nt], ah[mt], bb[nt >> 1][(nt & 1) * 2], bb[nt >> 1][(nt & 1) * 2 + 1]);
                    mma16(acc[mt][nt], al[mt], bb[nt >> 1][(nt & 1) * 2], bb[nt >> 1][(nt & 1) * 2 + 1]);
                }
            #pragma unroll
            for (int ntp = 0; ntp < 4; ntp++)
                ldm_x4_t(bb[ntp], sb + OFF_VL + swV(vr, v_c16b + ntp * 2));
            #pragma unroll
            for (int mt = 0; mt < 2; mt++)
                #pragma unroll
                for (int nt = 0; nt < 8; nt++)
                    mma16(acc[mt][nt], ah[mt], bb[nt >> 1][(nt & 1) * 2], bb[nt >> 1][(nt & 1) * 2 + 1]);
        }
    }
    __syncthreads();

    const int rb = by * 128 + wm * 32 + (lane >> 2);
    const int cb = bx * 128 + wn * 64 + (lane & 3) * 2;
    #pragma unroll
    for (int mt = 0; mt < 2; mt++)
        #pragma unroll
        for (int h = 0; h < 2; h++) {
            const int r = rb + mt * 16 + h * 8;
            float* Crow = out + ((long long)bz * N_SZ + r) * 1024 + cb;
            #pragma unroll
            for (int nt = 0; nt < 8; nt++)
                *reinterpret_cast<float2*>(Crow + nt * 8) =
                    make_float2(acc[mt][nt][h * 2], acc[mt][nt][h * 2 + 1]);
        }
}

// ---------------- conversions ----------------
__global__ __launch_bounds__(256)
void split_fp32(const float4* __restrict__ in, uint2* __restrict__ hi, uint2* __restrict__ lo, int n4)
{
    int i = blockIdx.x * 256 + threadIdx.x;
    if (i >= n4) return;
    float4 v = in[i];
    bf16 h0 = __float2bfloat16(v.x), h1 = __float2bfloat16(v.y);
    bf16 h2 = __float2bfloat16(v.z), h3 = __float2bfloat16(v.w);
    bf16 l0 = __float2bfloat16(v.x - __bfloat162float(h0));
    bf16 l1 = __float2bfloat16(v.y - __bfloat162float(h1));
    bf16 l2 = __float2bfloat16(v.z - __bfloat162float(h2));
    bf16 l3 = __float2bfloat16(v.w - __bfloat162float(h3));
    uint2 H, L;
    H.x = (uint32_t)__bfloat16_as_ushort(h0) | ((uint32_t)__bfloat16_as_ushort(h1) << 16);
    H.y = (uint32_t)__bfloat16_as_ushort(h2) | ((uint32_t)__bfloat16_as_ushort(h3) << 16);
    L.x = (uint32_t)__bfloat16_as_ushort(l0) | ((uint32_t)__bfloat16_as_ushort(l1) << 16);
    L.y = (uint32_t)__bfloat16_as_ushort(l2) | ((uint32_t)__bfloat16_as_ushort(l3) << 16);
    hi[i] = H; lo[i] = L;
}

__global__ __launch_bounds__(256)
void transpose_split3(const float* __restrict__ W0, const float* __restrict__ W1,
                      const float* __restrict__ W2,
                      bf16* __restrict__ T0h, bf16* __restrict__ T0l,
                      bf16* __restrict__ T1h, bf16* __restrict__ T1l,
                      bf16* __restrict__ T2h, bf16* __restrict__ T2l)
{
    const int z = blockIdx.z;
    const float* W = (z == 0) ? W0 : (z == 1) ? W1 : W2;
    bf16* Th = (z == 0) ? T0h : (z == 1) ? T1h : T2h;
    bf16* Tl = (z == 0) ? T0l : (z == 1) ? T1l : T2l;

    __shared__ float t[32][33];
    const int tx = threadIdx.x, ty = threadIdx.y;
    const int c0 = blockIdx.x * 32, r0 = blockIdx.y * 32;
    #pragma unroll
    for (int j = ty; j < 32; j += 8)
        t[j][tx] = W[(long long)(r0 + j) * D_SZ + c0 + tx];
    __syncthreads();
    #pragma unroll
    for (int j = ty; j < 32; j += 8) {
        float v = t[tx][j];
        bf16 h = __float2bfloat16(v);
        long long o = (long long)(c0 + j) * D_SZ + r0 + tx;
        Th[o] = h;
        Tl[o] = __float2bfloat16(v - __bfloat162float(h));
    }
}

// ---------------- single-pass causal softmax -> bf16 hi/lo P ----------------
__global__ __launch_bounds__(256)
void softmax_split(const float* __restrict__ S, bf16* __restrict__ Ph, bf16* __restrict__ Pl,
                   int n, float scale)
{
    const int i = blockIdx.x, b = blockIdx.y;
    const long long base = ((long long)b * n + i) * n;
    const float* row = S + base;
    const int L  = i + 1;
    const int Lw = ((i >> 7) + 1) << 7;
    const int tid = threadIdx.x;

    __shared__ float red[8];
    __shared__ float bc;

    float v[8];
    float m = -3.0e38f;
    #pragma unroll
    for (int k = 0; k < 8; k++) {
        const int j = tid + k * 256;
        float s = (j < L) ? row[j] * scale : -3.0e38f;
        v[k] = s;
        m = fmaxf(m, s);
    }
    #pragma unroll
    for (int o = 16; o > 0; o >>= 1) m = fmaxf(m, __shfl_xor_sync(0xffffffffu, m, o));
    if ((tid & 31) == 0) red[tid >> 5] = m;
    __syncthreads();
    if (tid < 32) {
        float t = (tid < 8) ? red[tid] : -3.0e38f;
        #pragma unroll
        for (int o = 16; o > 0; o >>= 1) t = fmaxf(t, __shfl_xor_sync(0xffffffffu, t, o));
        if (tid == 0) bc = t;
    }
    __syncthreads();
    m = bc;

    float sum = 0.0f;
    #pragma unroll
    for (int k = 0; k < 8; k++) {
        float e = __expf(v[k] - m);
        v[k] = e;
        sum += e;
    }
    #pragma unroll
    for (int o = 16; o > 0; o >>= 1) sum += __shfl_xor_sync(0xffffffffu, sum, o);
    __syncthreads();
    if ((tid & 31) == 0) red[tid >> 5] = sum;
    __syncthreads();
    if (tid < 32) {
        float t = (tid < 8) ? red[tid] : 0.0f;
        #pragma unroll
        for (int o = 16; o > 0; o >>= 1) t += __shfl_xor_sync(0xffffffffu, t, o);
        if (tid == 0) bc = t;
    }
    __syncthreads();
    const float inv = 1.0f / bc;

    #pragma unroll
    for (int k = 0; k < 8; k++) {
        const int j = tid + k * 256;
        if (j < Lw) {
            float p = v[k] * inv;
            bf16 h = __float2bfloat16(p);
            Ph[base + j] = h;
            Pl[base + j] = __float2bfloat16(p - __bfloat162float(h));
        }
    }
}

// ----------------------------------------------------------------------------
extern "C" void kernel_launch(void* const* d_in, const int* in_sizes, int n_in,
                              void* d_out, int out_size)
{
    const float* x  = (const float*)d_in[0];
    const float* Wq = (const float*)d_in[1];
    const float* Wk = (const float*)d_in[2];
    const float* Wv = (const float*)d_in[3];
    float* out = (float*)d_out;

    bf16 *xh, *xl, *Wqh, *Wql, *Wkh, *Wkl, *Wvh, *Wvl;
    bf16 *Qh, *Ql, *Kh, *Kl, *Vh, *Vl, *Ph, *Pl;
    float* S;
    cudaGetSymbolAddress((void**)&xh, g_xh);   cudaGetSymbolAddress((void**)&xl, g_xl);
    cudaGetSymbolAddress((void**)&Wqh, g_Wqh); cudaGetSymbolAddress((void**)&Wql, g_Wql);
    cudaGetSymbolAddress((void**)&Wkh, g_Wkh); cudaGetSymbolAddress((void**)&Wkl, g_Wkl);
    cudaGetSymbolAddress((void**)&Wvh, g_Wvh); cudaGetSymbolAddress((void**)&Wvl, g_Wvl);
    cudaGetSymbolAddress((void**)&Qh, g_Qh);   cudaGetSymbolAddress((void**)&Ql, g_Ql);
    cudaGetSymbolAddress((void**)&Kh, g_Kh);   cudaGetSymbolAddress((void**)&Kl, g_Kl);
    cudaGetSymbolAddress((void**)&Vh, g_Vh);   cudaGetSymbolAddress((void**)&Vl, g_Vl);
    cudaGetSymbolAddress((void**)&Ph, g_Ph);   cudaGetSymbolAddress((void**)&Pl, g_Pl);
    cudaGetSymbolAddress((void**)&S, g_S);

    cudaFuncSetAttribute(gemm_ab<0>, cudaFuncAttributeMaxDynamicSharedMemorySize, SMEM_AB);
    cudaFuncSetAttribute(gemm_ab<1>, cudaFuncAttributeMaxDynamicSharedMemorySize, SMEM_AB);
    cudaFuncSetAttribute(gemm_pv,    cudaFuncAttributeMaxDynamicSharedMemorySize, SMEM_PV);

    split_fp32<<<(B_SZ * N_SZ * D_SZ / 4 + 255) / 256, 256>>>(
        (const float4*)x, (uint2*)xh, (uint2*)xl, B_SZ * N_SZ * D_SZ / 4);
    transpose_split3<<<dim3(32, 32, 3), dim3(32, 8)>>>(
        Wq, Wk, Wv, Wqh, Wql, Wkh, Wkl, Wvh, Wvl);

    // 1) QK projection (1024 tiles)
    gemm_ab<0><<<dim3(8, 64, 2), 256, SMEM_AB>>>(
        xh, xl, Wqh, Wql, Wkh, Wkl, nullptr, nullptr,
        Qh, Ql, Kh, Kl, nullptr);

    // 2) merged S (544 tiles) + V-projection (512 tiles)
    gemm_ab<1><<<dim3(1056, 1, 1), 256, SMEM_AB>>>(
        Qh, Ql, Kh, Kl, xh, xl, Wvh, Wvl,
        Vh, Vl, nullptr, nullptr, S);

    // 3) softmax -> P hi/lo
    softmax_split<<<dim3(N_SZ, B_SZ), 256>>>(S, Ph, Pl, N_SZ, 1.0f / 32.0f);

    // 4) out = P @ V (LPT)
    gemm_pv<<<dim3(512, 1, 1), 256, SMEM_PV>>>(Ph, Pl, Vh, Vl, out);
}

// round 10
// speedup vs baseline: 4.1677x; 1.1418x over previous
#include <cuda_runtime.h>
#include <cuda_fp16.h>
#include <cstdint>
#include <cmath>

// ============================================================================
// CausalAttention b=4, n=2048, d=1024 — mma.sync fp16 split-precision.
// R10: fp16 hi/lo split (11-bit mantissa). QKV proj = 3-pass (full accuracy);
//      S and PV = 2-pass (keep (Ah+Al)@Bh, drop A@Bl; ~2.4e-4 each).
//      PV never reads Vl -> skip those loads. R8/R9 chassis otherwise.
// ============================================================================

#define B_SZ 4
#define N_SZ 2048
#define D_SZ 1024
typedef __half h16;

static constexpr long long ND = (long long)N_SZ * D_SZ;
static constexpr long long NN = (long long)N_SZ * N_SZ;

// ---------------- scratch ----------------
__device__ h16   g_xh [(size_t)B_SZ*N_SZ*D_SZ];
__device__ h16   g_xl [(size_t)B_SZ*N_SZ*D_SZ];
__device__ h16   g_Wqh[(size_t)D_SZ*D_SZ];
__device__ h16   g_Wql[(size_t)D_SZ*D_SZ];
__device__ h16   g_Wkh[(size_t)D_SZ*D_SZ];
__device__ h16   g_Wkl[(size_t)D_SZ*D_SZ];
__device__ h16   g_Wvh[(size_t)D_SZ*D_SZ];
__device__ h16   g_Wvl[(size_t)D_SZ*D_SZ];
__device__ h16   g_Qh [(size_t)B_SZ*N_SZ*D_SZ];
__device__ h16   g_Ql [(size_t)B_SZ*N_SZ*D_SZ];
__device__ h16   g_Kh [(size_t)B_SZ*N_SZ*D_SZ];
__device__ h16   g_Kl [(size_t)B_SZ*N_SZ*D_SZ];
__device__ h16   g_Vh [(size_t)B_SZ*N_SZ*D_SZ];
__device__ float g_S  [(size_t)B_SZ*N_SZ*N_SZ];
__device__ h16   g_Ph [(size_t)B_SZ*N_SZ*N_SZ];
__device__ h16   g_Pl [(size_t)B_SZ*N_SZ*N_SZ];

// ---------------- helpers ----------------
__device__ __forceinline__ uint32_t smem_u32(const void* p) {
    uint32_t a;
    asm("{ .reg .u64 t; cvta.to.shared.u64 t, %1; cvt.u32.u64 %0, t; }" : "=r"(a) : "l"(p));
    return a;
}
__device__ __forceinline__ void cp16(uint32_t dst, const void* src) {
    asm volatile("cp.async.cg.shared.global [%0], [%1], 16;" :: "r"(dst), "l"(src));
}
#define CP_COMMIT() asm volatile("cp.async.commit_group;" ::: "memory")
#define CP_WAIT(n)  asm volatile("cp.async.wait_group %0;" :: "n"(n) : "memory")

__device__ __forceinline__ void ldm_x4(uint32_t* r, uint32_t addr) {
    asm volatile("ldmatrix.sync.aligned.m8n8.x4.shared.b16 {%0,%1,%2,%3}, [%4];"
                 : "=r"(r[0]), "=r"(r[1]), "=r"(r[2]), "=r"(r[3]) : "r"(addr));
}
__device__ __forceinline__ void ldm_x4_t(uint32_t* r, uint32_t addr) {
    asm volatile("ldmatrix.sync.aligned.m8n8.x4.trans.shared.b16 {%0,%1,%2,%3}, [%4];"
                 : "=r"(r[0]), "=r"(r[1]), "=r"(r[2]), "=r"(r[3]) : "r"(addr));
}
__device__ __forceinline__ void mma16(float* c, const uint32_t* a, uint32_t b0, uint32_t b1) {
    asm volatile("mma.sync.aligned.m16n8k16.row.col.f32.f16.f16.f32 "
                 "{%0,%1,%2,%3}, {%4,%5,%6,%7}, {%8,%9}, {%0,%1,%2,%3};"
                 : "+f"(c[0]), "+f"(c[1]), "+f"(c[2]), "+f"(c[3])
                 : "r"(a[0]), "r"(a[1]), "r"(a[2]), "r"(a[3]), "r"(b0), "r"(b1));
}

// fp16 hi/lo split
__device__ __forceinline__ void split2(float v, h16& h, h16& l) {
    h = __float2half_rn(v);
    l = __float2half_rn(v - __half2float(h));
}
__device__ __forceinline__ uint32_t packh(h16 a, h16 b) {
    return (uint32_t)__half_as_ushort(a) | ((uint32_t)__half_as_ushort(b) << 16);
}

// XOR swizzles (pad-free, conflict-free)
__device__ __forceinline__ uint32_t swAB(int row, int c16) {   // 128 rows x 64B
    return (uint32_t)row * 64 + (uint32_t)((c16 ^ ((row >> 1) & 3)) << 4);
}
__device__ __forceinline__ uint32_t swV(int row, int c16) {    // 32 rows x 256B
    return (uint32_t)row * 256 + (uint32_t)((c16 ^ (row & 7)) << 4);
}

static constexpr uint32_t TILE_B  = 128 * 64;               // 8192
static constexpr uint32_t STAGE_B = 4 * TILE_B;             // 32768
static constexpr uint32_t OFF_AH = 0, OFF_AL = TILE_B, OFF_BH = 2*TILE_B, OFF_BL = 3*TILE_B;
static constexpr uint32_t SMEM_AB = 3 * STAGE_B;            // 98304
static constexpr uint32_t V_T  = 32 * 256;                  // 8192
static constexpr uint32_t OFF_VH = 2*TILE_B;
static constexpr uint32_t STGV = 2*TILE_B + V_T;            // 24576
static constexpr uint32_t SMEM_PV = 3 * STGV;               // 73728

// ----------------------------------------------------------------------------
// MODE 0: QK projection (3-pass). grid (8, 64, 2).
// MODE 1: merged S (2-pass) + V-proj (3-pass). grid (1056,1,1).
// ----------------------------------------------------------------------------
template <int MODE>
__global__ __launch_bounds__(256, 2)
void gemm_ab(const h16* __restrict__ Ah_, const h16* __restrict__ Al_,
             const h16* __restrict__ B0h, const h16* __restrict__ B0l,
             const h16* __restrict__ B1h, const h16* __restrict__ B1l,
             const h16* __restrict__ B2h, const h16* __restrict__ B2l,
             h16* C0h, h16* C0l, h16* C1h, h16* C1l,
             float* Sout)
{
    int bx, by, bz;
    bool isS = false;
    if (MODE == 0) {
        bx = blockIdx.x; by = blockIdx.y; bz = blockIdx.z;
    } else {
        const int Lb = blockIdx.x;
        if (Lb < 544) {
            isS = true;
            bz = Lb & 3;
            const int t = Lb >> 2;
            by = (int)((sqrtf(8.f * (float)t + 1.f) - 1.f) * 0.5f);
            while ((by + 1) * (by + 2) / 2 <= t) by++;
            while (by * (by + 1) / 2 > t) by--;
            bx = t - by * (by + 1) / 2;
        } else {
            const int t2 = Lb - 544;
            bx = t2 & 7; by = t2 >> 3; bz = 0;
        }
    }
    const bool pass3 = (MODE == 0) || !isS;   // S runs 2-pass

    extern __shared__ char smem[];
    const uint32_t su = smem_u32(smem);
    const int tid = threadIdx.x;
    const int lane = tid & 31, wid = tid >> 5;
    const int wm = wid & 3, wn = wid >> 2;

    const h16 *pAh, *pAl, *pBh, *pBl;
    if (MODE == 0) {
        pAh = Ah_ + (long long)(by * 128) * 1024;
        pAl = Al_ + (long long)(by * 128) * 1024;
        const h16* bh = (bz == 0) ? B0h : B1h;
        const h16* bl = (bz == 0) ? B0l : B1l;
        pBh = bh + (long long)(bx * 128) * 1024;
        pBl = bl + (long long)(bx * 128) * 1024;
    } else if (isS) {
        pAh = Ah_ + bz * ND + (long long)(by * 128) * 1024;
        pAl = Al_ + bz * ND + (long long)(by * 128) * 1024;
        pBh = B0h + bz * ND + (long long)(bx * 128) * 1024;
        pBl = B0l + bz * ND + (long long)(bx * 128) * 1024;   // unused (2-pass)
    } else {                                  // V-proj: A = x, B = Wv
        pAh = B1h + (long long)(by * 128) * 1024;
        pAl = B1l + (long long)(by * 128) * 1024;
        pBh = B2h + (long long)(bx * 128) * 1024;
        pBl = B2l + (long long)(bx * 128) * 1024;
    }

    auto load_stage = [&](int stg, int k0) {
        const uint32_t sb = su + (uint32_t)stg * STAGE_B;
        #pragma unroll
        for (int it = 0; it < 2; it++) {
            const int ch = tid + it * 256;
            const int row = ch >> 2, c = ch & 3;
            const uint32_t so = swAB(row, c);
            const long long go = (long long)row * 1024 + k0 + c * 8;
            cp16(sb + OFF_AH + so, pAh + go);
            cp16(sb + OFF_AL + so, pAl + go);
            cp16(sb + OFF_BH + so, pBh + go);
            if (pass3) cp16(sb + OFF_BL + so, pBl + go);
        }
    };

    const int a_row = wm * 32 + (lane & 15);
    const int a_c16 = lane >> 4;
    const int b_row = wn * 64 + ((lane >> 4) << 3) + (lane & 7);
    const int b_c16 = (lane >> 3) & 1;
    const int kpar  = wid & 1;

    float acc[2][8][4] = {};
    const int nchunks = 32;

    load_stage(0, 0);  CP_COMMIT();
    load_stage(1, 32); CP_COMMIT();
    int ld_stg = 2;

    for (int i = 0; i < nchunks; i++) {
        if (i + 1 < nchunks) { CP_WAIT(1); } else { CP_WAIT(0); }
        __syncthreads();
        if (i + 2 < nchunks) {
            load_stage(ld_stg, (i + 2) * 32); CP_COMMIT();
            ld_stg = (ld_stg == 2) ? 0 : ld_stg + 1;
        }
        const uint32_t sb = su + (uint32_t)(i % 3) * STAGE_B;
        #pragma unroll
        for (int ksi = 0; ksi < 2; ksi++) {
            const int ks = ksi ^ kpar;
            const int ca = ks * 2 + a_c16;
            const int cbv = ks * 2 + b_c16;
            uint32_t ah[2][4], al[2][4], bb[4][4];
            #pragma unroll
            for (int mt = 0; mt < 2; mt++) {
                ldm_x4(ah[mt], sb + OFF_AH + swAB(a_row + mt * 16, ca));
                ldm_x4(al[mt], sb + OFF_AL + swAB(a_row + mt * 16, ca));
            }
            #pragma unroll
            for (int ntp = 0; ntp < 4; ntp++)
                ldm_x4(bb[ntp], sb + OFF_BH + swAB(b_row + ntp * 16, cbv));
            #pragma unroll
            for (int mt = 0; mt < 2; mt++)
                #pragma unroll
                for (int nt = 0; nt < 8; nt++) {
                    mma16(acc[mt][nt], ah[mt], bb[nt >> 1][(nt & 1) * 2], bb[nt >> 1][(nt & 1) * 2 + 1]);
                    mma16(acc[mt][nt], al[mt], bb[nt >> 1][(nt & 1) * 2], bb[nt >> 1][(nt & 1) * 2 + 1]);
                }
            if (pass3) {
                #pragma unroll
                for (int ntp = 0; ntp < 4; ntp++)
                    ldm_x4(bb[ntp], sb + OFF_BL + swAB(b_row + ntp * 16, cbv));
                #pragma unroll
                for (int mt = 0; mt < 2; mt++)
                    #pragma unroll
                    for (int nt = 0; nt < 8; nt++)
                        mma16(acc[mt][nt], ah[mt], bb[nt >> 1][(nt & 1) * 2], bb[nt >> 1][(nt & 1) * 2 + 1]);
            }
        }
    }
    __syncthreads();

    const int rb = by * 128 + wm * 32 + (lane >> 2);
    const int cb = bx * 128 + wn * 64 + (lane & 3) * 2;
    #pragma unroll
    for (int mt = 0; mt < 2; mt++)
        #pragma unroll
        for (int h = 0; h < 2; h++) {
            const int r = rb + mt * 16 + h * 8;
            if (MODE == 1 && isS) {
                float* Crow = Sout + bz * NN + (long long)r * N_SZ + cb;
                #pragma unroll
                for (int nt = 0; nt < 8; nt++)
                    *reinterpret_cast<float2*>(Crow + nt * 8) =
                        make_float2(acc[mt][nt][h * 2], acc[mt][nt][h * 2 + 1]);
            } else if (MODE == 0) {
                h16* Ch = ((bz == 0) ? C0h : C1h) + (long long)r * 1024 + cb;
                h16* Cl = ((bz == 0) ? C0l : C1l) + (long long)r * 1024 + cb;
                #pragma unroll
                for (int nt = 0; nt < 8; nt++) {
                    h16 h0, l0, h1, l1;
                    split2(acc[mt][nt][h * 2], h0, l0);
                    split2(acc[mt][nt][h * 2 + 1], h1, l1);
                    *reinterpret_cast<uint32_t*>(Ch + nt * 8) = packh(h0, h1);
                    *reinterpret_cast<uint32_t*>(Cl + nt * 8) = packh(l0, l1);
                }
            } else {                           // V-proj: hi only (PV is 2-pass)
                h16* Ch = C0h + (long long)r * 1024 + cb;
                #pragma unroll
                for (int nt = 0; nt < 8; nt++) {
                    h16 h0 = __float2half_rn(acc[mt][nt][h * 2]);
                    h16 h1 = __float2half_rn(acc[mt][nt][h * 2 + 1]);
                    *reinterpret_cast<uint32_t*>(Ch + nt * 8) = packh(h0, h1);
                }
            }
        }
}

// ----------------------------------------------------------------------------
// out = P @ Vh (2-pass: (Ph+Pl)@Vh). grid (512,1,1), LPT; K limit (by+1)*128.
// ----------------------------------------------------------------------------
__global__ __launch_bounds__(256, 2)
void gemm_pv(const h16* __restrict__ Ph_, const h16* __restrict__ Pl_,
             const h16* __restrict__ Vh_, float* __restrict__ out)
{
    const int Lb = blockIdx.x;
    const int by = 15 - (Lb >> 5);
    const int rr = Lb & 31;
    const int bx = rr & 7, bz = rr >> 3;

    extern __shared__ char smem[];
    const uint32_t su = smem_u32(smem);
    const int tid = threadIdx.x;
    const int lane = tid & 31, wid = tid >> 5;
    const int wm = wid & 3, wn = wid >> 2;

    const h16* pAh = Ph_ + bz * NN + (long long)(by * 128) * N_SZ;
    const h16* pAl = Pl_ + bz * NN + (long long)(by * 128) * N_SZ;
    const h16* pVh = Vh_ + bz * ND + bx * 128;

    const int nchunks = (by + 1) * 4;

    auto load_stage = [&](int stg, int k0) {
        const uint32_t sb = su + (uint32_t)stg * STGV;
        #pragma unroll
        for (int it = 0; it < 2; it++) {
            const int ch = tid + it * 256;
            const int row = ch >> 2, c = ch & 3;
            const uint32_t so = swAB(row, c);
            const long long go = (long long)row * N_SZ + k0 + c * 8;
            cp16(sb + OFF_AH + so, pAh + go);
            cp16(sb + OFF_AL + so, pAl + go);
        }
        {
            const int row = tid >> 4, c = tid & 15;   // 256 thr cover 32x16 chunks... 2 iters
            const uint32_t so = swV(row, c);
            const long long go = (long long)(k0 + row) * 1024 + c * 8;
            cp16(sb + OFF_VH + so, pVh + go);
            const int row2 = row + 16;
            const uint32_t so2 = swV(row2, c);
            const long long go2 = (long long)(k0 + row2) * 1024 + c * 8;
            cp16(sb + OFF_VH + so2, pVh + go2);
        }
    };

    const int a_row = wm * 32 + (lane & 15);
    const int a_c16 = lane >> 4;
    const int v_row  = (lane & 7) + ((lane >> 3) & 1) * 8;
    const int v_c16b = wn * 8 + ((lane >> 4) & 1);
    const int kpar = wid & 1;

    float acc[2][8][4] = {};

    load_stage(0, 0);  CP_COMMIT();
    load_stage(1, 32); CP_COMMIT();
    int ld_stg = 2;

    for (int i = 0; i < nchunks; i++) {
        if (i + 1 < nchunks) { CP_WAIT(1); } else { CP_WAIT(0); }
        __syncthreads();
        if (i + 2 < nchunks) {
            load_stage(ld_stg, (i + 2) * 32); CP_COMMIT();
            ld_stg = (ld_stg == 2) ? 0 : ld_stg + 1;
        }
        const uint32_t sb = su + (uint32_t)(i % 3) * STGV;
        #pragma unroll
        for (int ksi = 0; ksi < 2; ksi++) {
            const int ks = ksi ^ kpar;
            const int ca = ks * 2 + a_c16;
            const int vr = ks * 16 + v_row;
            uint32_t ah[2][4], al[2][4], bb[4][4];
            #pragma unroll
            for (int mt = 0; mt < 2; mt++) {
                ldm_x4(ah[mt], sb + OFF_AH + swAB(a_row + mt * 16, ca));
                ldm_x4(al[mt], sb + OFF_AL + swAB(a_row + mt * 16, ca));
            }
            #pragma unroll
            for (int ntp = 0; ntp < 4; ntp++)
                ldm_x4_t(bb[ntp], sb + OFF_VH + swV(vr, v_c16b + ntp * 2));
            #pragma unroll
            for (int mt = 0; mt < 2; mt++)
                #pragma unroll
                for (int nt = 0; nt < 8; nt++) {
                    mma16(acc[mt][nt], ah[mt], bb[nt >> 1][(nt & 1) * 2], bb[nt >> 1][(nt & 1) * 2 + 1]);
                    mma16(acc[mt][nt], al[mt], bb[nt >> 1][(nt & 1) * 2], bb[nt >> 1][(nt & 1) * 2 + 1]);
                }
        }
    }
    __syncthreads();

    const int rb = by * 128 + wm * 32 + (lane >> 2);
    const int cb = bx * 128 + wn * 64 + (lane & 3) * 2;
    #pragma unroll
    for (int mt = 0; mt < 2; mt++)
        #pragma unroll
        for (int h = 0; h < 2; h++) {
            const int r = rb + mt * 16 + h * 8;
            float* Crow = out + ((long long)bz * N_SZ + r) * 1024 + cb;
            #pragma unroll
            for (int nt = 0; nt < 8; nt++)
                *reinterpret_cast<float2*>(Crow + nt * 8) =
                    make_float2(acc[mt][nt][h * 2], acc[mt][nt][h * 2 + 1]);
        }
}

// ---------------- conversions ----------------
__global__ __launch_bounds__(256)
void split_fp32(const float4* __restrict__ in, uint2* __restrict__ hi, uint2* __restrict__ lo, int n4)
{
    int i = blockIdx.x * 256 + threadIdx.x;
    if (i >= n4) return;
    float4 v = in[i];
    h16 h0, l0, h1, l1, h2, l2, h3, l3;
    split2(v.x, h0, l0); split2(v.y, h1, l1);
    split2(v.z, h2, l2); split2(v.w, h3, l3);
    uint2 H, L;
    H.x = packh(h0, h1); H.y = packh(h2, h3);
    L.x = packh(l0, l1); L.y = packh(l2, l3);
    hi[i] = H; lo[i] = L;
}

__global__ __launch_bounds__(256)
void transpose_split3(const float* __restrict__ W0, const float* __restrict__ W1,
                      const float* __restrict__ W2,
                      h16* __restrict__ T0h, h16* __restrict__ T0l,
                      h16* __restrict__ T1h, h16* __restrict__ T1l,
                      h16* __restrict__ T2h, h16* __restrict__ T2l)
{
    const int z = blockIdx.z;
    const float* W = (z == 0) ? W0 : (z == 1) ? W1 : W2;
    h16* Th = (z == 0) ? T0h : (z == 1) ? T1h : T2h;
    h16* Tl = (z == 0) ? T0l : (z == 1) ? T1l : T2l;

    __shared__ float t[32][33];
    const int tx = threadIdx.x, ty = threadIdx.y;
    const int c0 = blockIdx.x * 32, r0 = blockIdx.y * 32;
    #pragma unroll
    for (int j = ty; j < 32; j += 8)
        t[j][tx] = W[(long long)(r0 + j) * D_SZ + c0 + tx];
    __syncthreads();
    #pragma unroll
    for (int j = ty; j < 32; j += 8) {
        float v = t[tx][j];
        h16 h, l;
        split2(v, h, l);
        long long o = (long long)(c0 + j) * D_SZ + r0 + tx;
        Th[o] = h;
        Tl[o] = l;
    }
}

// ---------------- single-pass causal softmax -> fp16 hi/lo P ----------------
__global__ __launch_bounds__(256)
void softmax_split(const float* __restrict__ S, h16* __restrict__ Ph, h16* __restrict__ Pl,
                   int n, float scale)
{
    const int i = blockIdx.x, b = blockIdx.y;
    const long long base = ((long long)b * n + i) * n;
    const float* row = S + base;
    const int L  = i + 1;
    const int Lw = ((i >> 7) + 1) << 7;
    const int tid = threadIdx.x;

    __shared__ float red[8];
    __shared__ float bc;

    float v[8];
    float m = -3.0e38f;
    #pragma unroll
    for (int k = 0; k < 8; k++) {
        const int j = tid + k * 256;
        float s = (j < L) ? row[j] * scale : -3.0e38f;
        v[k] = s;
        m = fmaxf(m, s);
    }
    #pragma unroll
    for (int o = 16; o > 0; o >>= 1) m = fmaxf(m, __shfl_xor_sync(0xffffffffu, m, o));
    if ((tid & 31) == 0) red[tid >> 5] = m;
    __syncthreads();
    if (tid < 32) {
        float t = (tid < 8) ? red[tid] : -3.0e38f;
        #pragma unroll
        for (int o = 16; o > 0; o >>= 1) t = fmaxf(t, __shfl_xor_sync(0xffffffffu, t, o));
        if (tid == 0) bc = t;
    }
    __syncthreads();
    m = bc;

    float sum = 0.0f;
    #pragma unroll
    for (int k = 0; k < 8; k++) {
        float e = __expf(v[k] - m);
        v[k] = e;
        sum += e;
    }
    #pragma unroll
    for (int o = 16; o > 0; o >>= 1) sum += __shfl_xor_sync(0xffffffffu, sum, o);
    __syncthreads();
    if ((tid & 31) == 0) red[tid >> 5] = sum;
    __syncthreads();
    if (tid < 32) {
        float t = (tid < 8) ? red[tid] : 0.0f;
        #pragma unroll
        for (int o = 16; o > 0; o >>= 1) t += __shfl_xor_sync(0xffffffffu, t, o);
        if (tid == 0) bc = t;
    }
    __syncthreads();
    const float inv = 1.0f / bc;

    #pragma unroll
    for (int k = 0; k < 8; k++) {
        const int j = tid + k * 256;
        if (j < Lw) {
            float p = v[k] * inv;
            h16 h, l;
            split2(p, h, l);
            Ph[base + j] = h;
            Pl[base + j] = l;
        }
    }
}

// ----------------------------------------------------------------------------
extern "C" void kernel_launch(void* const* d_in, const int* in_sizes, int n_in,
                              void* d_out, int out_size)
{
    const float* x  = (const float*)d_in[0];
    const float* Wq = (const float*)d_in[1];
    const float* Wk = (const float*)d_in[2];
    const float* Wv = (const float*)d_in[3];
    float* out = (float*)d_out;

    h16 *xh, *xl, *Wqh, *Wql, *Wkh, *Wkl, *Wvh, *Wvl;
    h16 *Qh, *Ql, *Kh, *Kl, *Vh, *Ph, *Pl;
    float* S;
    cudaGetSymbolAddress((void**)&xh, g_xh);   cudaGetSymbolAddress((void**)&xl, g_xl);
    cudaGetSymbolAddress((void**)&Wqh, g_Wqh); cudaGetSymbolAddress((void**)&Wql, g_Wql);
    cudaGetSymbolAddress((void**)&Wkh, g_Wkh); cudaGetSymbolAddress((void**)&Wkl, g_Wkl);
    cudaGetSymbolAddress((void**)&Wvh, g_Wvh); cudaGetSymbolAddress((void**)&Wvl, g_Wvl);
    cudaGetSymbolAddress((void**)&Qh, g_Qh);   cudaGetSymbolAddress((void**)&Ql, g_Ql);
    cudaGetSymbolAddress((void**)&Kh, g_Kh);   cudaGetSymbolAddress((void**)&Kl, g_Kl);
    cudaGetSymbolAddress((void**)&Vh, g_Vh);
    cudaGetSymbolAddress((void**)&Ph, g_Ph);   cudaGetSymbolAddress((void**)&Pl, g_Pl);
    cudaGetSymbolAddress((void**)&S, g_S);

    cudaFuncSetAttribute(gemm_ab<0>, cudaFuncAttributeMaxDynamicSharedMemorySize, SMEM_AB);
    cudaFuncSetAttribute(gemm_ab<1>, cudaFuncAttributeMaxDynamicSharedMemorySize, SMEM_AB);
    cudaFuncSetAttribute(gemm_pv,    cudaFuncAttributeMaxDynamicSharedMemorySize, SMEM_PV);

    split_fp32<<<(B_SZ * N_SZ * D_SZ / 4 + 255) / 256, 256>>>(
        (const float4*)x, (uint2*)xh, (uint2*)xl, B_SZ * N_SZ * D_SZ / 4);
    transpose_split3<<<dim3(32, 32, 3), dim3(32, 8)>>>(
        Wq, Wk, Wv, Wqh, Wql, Wkh, Wkl, Wvh, Wvl);

    // 1) QK projection (3-pass)
    gemm_ab<0><<<dim3(8, 64, 2), 256, SMEM_AB>>>(
        xh, xl, Wqh, Wql, Wkh, Wkl, nullptr, nullptr,
        Qh, Ql, Kh, Kl, nullptr);

    // 2) merged S (2-pass) + V-projection (3-pass, hi-only output)
    gemm_ab<1><<<dim3(1056, 1, 1), 256, SMEM_AB>>>(
        Qh, Ql, Kh, Kl, xh, xl, Wvh, Wvl,
        Vh, nullptr, nullptr, nullptr, S);

    // 3) softmax -> P hi/lo
    softmax_split<<<dim3(N_SZ, B_SZ), 256>>>(S, Ph, Pl, N_SZ, 1.0f / 32.0f);

    // 4) out = (Ph+Pl) @ Vh (2-pass, LPT)
    gemm_pv<<<dim3(512, 1, 1), 256, SMEM_PV>>>(Ph, Pl, Vh, out);
}